// round 6
// baseline (speedup 1.0000x reference)
#include <cuda_runtime.h>
#include <math.h>

#define Bb 8
#define Tt 24
#define Nn 768
#define Ee 24576
#define Hh 64
#define BE 196608              // B*E
#define PRED_ELEMS (Bb*Tt*Nn)  // 147456

typedef unsigned long long u64;

// ---------------- packed f32x2 helpers (sm_100a FFMA2) ----------------
__device__ __forceinline__ u64 pk2(float x){
  u64 r; asm("mov.b64 %0,{%1,%1};":"=l"(r):"f"(x)); return r;
}
__device__ __forceinline__ void fma2(u64& d, u64 a, u64 b){
  asm("fma.rn.f32x2 %0,%1,%2,%0;":"+l"(d):"l"(a),"l"(b));
}
__device__ __forceinline__ float2 up2(u64 v){
  float2 f; asm("mov.b64 {%0,%1},%2;":"=f"(f.x),"=f"(f.y):"l"(v)); return f;
}

// ---------------- device scratch (static, no allocs) ----------------
__device__ float g_stat[4];          // mean0, mean1, rstd0, rstd1 (ddof=1)
__device__ float g_hn[Bb*Nn];
__device__ float g_sumhn[Bb];
__device__ int   g_cnt_raw[Nn];
__device__ int   g_rowptr[Nn+1];
__device__ int   g_cursor[Nn];
__device__ int   g_colidx[Ee];
__device__ int   g_cnt[Nn];          // deduped per-row counts
__device__ float g_erep[Tt*BE];      // 18.9 MB

// ---------------- prep: edge_attr mean/std (ddof=1) ----------------
__global__ void kstat(const float* __restrict__ eattr){
  __shared__ double red[1024];
  int tid = threadIdx.x;
  double s0=0,s1=0,q0=0,q1=0;
  for (int e=tid; e<Ee; e+=1024){
    double a=eattr[2*e], b=eattr[2*e+1];
    s0+=a; s1+=b; q0+=a*a; q1+=b*b;
  }
  double vals[4]={s0,s1,q0,q1};
  double out[4];
  for (int v=0; v<4; ++v){
    red[tid]=vals[v]; __syncthreads();
    for (int off=512; off; off>>=1){ if (tid<off) red[tid]+=red[tid+off]; __syncthreads(); }
    out[v]=red[0]; __syncthreads();
  }
  if (tid==0){
    double m0=out[0]/Ee, m1=out[1]/Ee;
    double v0=(out[2]-out[0]*out[0]/Ee)/(double)(Ee-1);
    double v1=(out[3]-out[1]*out[1]/Ee)/(double)(Ee-1);
    g_stat[0]=(float)m0; g_stat[1]=(float)m1;
    g_stat[2]=(float)(1.0/sqrt(v0)); g_stat[3]=(float)(1.0/sqrt(v1));
  }
  if (tid<Nn) g_cnt_raw[tid]=0;
}

__global__ void kcount(const int* __restrict__ eidx){
  int e = blockIdx.x*256+threadIdx.x;
  if (e<Ee) atomicAdd(&g_cnt_raw[eidx[Ee+e]],1);
}

__global__ void kscan(){
  __shared__ int a[Nn];
  int t=threadIdx.x;
  if (t<Nn) a[t]=g_cnt_raw[t];
  __syncthreads();
  for (int d=1; d<Nn; d<<=1){
    int v=0;
    if (t<Nn && t>=d) v=a[t-d];
    __syncthreads();
    if (t<Nn) a[t]+=v;
    __syncthreads();
  }
  if (t<Nn){ g_rowptr[t+1]=a[t]; g_cursor[t]=a[t]-g_cnt_raw[t]; }
  if (t==0) g_rowptr[0]=0;
}

__global__ void kfill(const int* __restrict__ eidx){
  int e = blockIdx.x*256+threadIdx.x;
  if (e<Ee){ int pos=atomicAdd(&g_cursor[eidx[Ee+e]],1); g_colidx[pos]=e; }
}

// canonicalize: sort each row by edge id, dedup by src keeping LAST edge
__global__ void kfix(const int* __restrict__ eidx){
  int t = blockIdx.x*256+threadIdx.x;
  if (t>=Nn) return;
  int rs=g_rowptr[t], re=g_rowptr[t+1];
  for (int i=rs+1;i<re;i++){
    int key=g_colidx[i]; int j=i-1;
    while(j>=rs && g_colidx[j]>key){ g_colidx[j+1]=g_colidx[j]; j--; }
    g_colidx[j+1]=key;
  }
  int w=rs;
  for (int i=rs;i<re;i++){
    int e=g_colidx[i]; int src=eidx[e];
    bool later=false;
    for (int j2=i+1;j2<re;j2++){ if (eidx[g_colidx[j2]]==src){later=true;break;} }
    if (!later) g_colidx[w++]=e;
  }
  g_cnt[t]=w-rs;
}

__global__ void khn(const float* __restrict__ pm25,
                    const float* __restrict__ Wn, const float* __restrict__ bn){
  __shared__ float red[256];
  int b=blockIdx.x, t=threadIdx.x;
  float w=Wn[0], bb=bn[0];
  float s=0.f;
  for (int n=t;n<Nn;n+=256){ float h=pm25[b*Nn+n]*w+bb; g_hn[b*Nn+n]=h; s+=h; }
  red[t]=s; __syncthreads();
  for(int off=128;off;off>>=1){ if(t<off) red[t]+=red[t+off]; __syncthreads(); }
  if(t==0) g_sumhn[b]=red[0];
}

// ---------------- main GRU + MLP: 64 rows/block, h in SMEM, FFMA2 inner loops ----------------
__global__ void __launch_bounds__(256,2) kgru(
    const float* __restrict__ feature, const int* __restrict__ eidx,
    const float* __restrict__ eattr,   const float* __restrict__ wmean,
    const float* __restrict__ wstd,    const float* __restrict__ W_ih,
    const float* __restrict__ W_hh,    const float* __restrict__ b_ih,
    const float* __restrict__ b_hh,    const float* __restrict__ W1,
    const float* __restrict__ b1,      const float* __restrict__ W2,
    const float* __restrict__ b2)
{
  extern __shared__ float sm[];
  float* sW  = sm;            // 64x192 W_hh (k-major)
  float* sW1v= sW + 12288;    // 64x64
  float* sh  = sW1v + 4096;   // 64 rows x 64
  float* sWih= sh + 4096;     // 3x192
  float* sbih= sWih+576;      // 192
  float* sbhh= sbih+192;      // 192
  float* sb1 = sbhh+192;      // 64
  float* sW2v= sb1+64;        // 64
  float* sEA0= sW2v+64;       // 64
  float* sEA1= sEA0+64;       // 64
  float* sDIR= sEA1+64;       // 64
  float* sC3D= sDIR+64;       // 64
  float* sEW = sC3D+64;       // 64
  int*   sSRC= (int*)(sEW+64);// 64

  const int tid  = threadIdx.x;
  const int base = blockIdx.x*64;   // 64 | E so batch constant per block
  const int bIdx = base / Ee;
  const int e0   = base % Ee;

  for (int i=tid;i<3072;i+=256) ((float4*)sW)[i]   = ((const float4*)W_hh)[i];
  for (int i=tid;i<1024;i+=256) ((float4*)sW1v)[i] = ((const float4*)W1)[i];
  for (int i=tid;i<576;i+=256) sWih[i]=W_ih[i];
  for (int i=tid;i<192;i+=256){ sbih[i]=b_ih[i]; sbhh[i]=b_hh[i]; }
  if (tid<64){ sb1[tid]=b1[tid]; sW2v[tid]=W2[tid]; }
  if (tid<64){
    int e=e0+tid;
    sSRC[tid]=eidx[e];
    float dd=eattr[2*e], dr=eattr[2*e+1];
    sDIR[tid]=dr;
    sC3D[tid]=3.f/dd;
    sEA0[tid]=(dd-g_stat[0])*g_stat[2];
    sEA1[tid]=(dr-g_stat[1])*g_stat[3];
  }
  for (int i=tid;i<4096;i+=256) sh[i]=0.f;   // en0 = zeros
  const float wm0=wmean[0], wm1=wmean[1], ws0=wstd[0], ws1=wstd[1];
  const float b2v=b2[0];
  __syncthreads();

  // thread tile: 2 rows x 8 cols
  const int jg = tid & 7;     // 8 j-groups of 8
  const int rp = tid >> 3;    // 32 row-pairs
  const int j0 = jg*8;
  const int r0 = rp*2;

  for (int t=0;t<Tt;t++){
    // --- edge weight for this step ---
    if (tid<64){
      const float* fp = feature + (((bIdx*25)+1+t)*Nn + sSRC[tid])*4 + 2;
      float speed = fp[0]*ws0+wm0;
      float wdir  = fp[1]*ws1+wm1;
      float ew = sC3D[tid]*speed*cosf(sDIR[tid]-wdir);
      sEW[tid] = fmaxf(ew,0.f);
    }
    __syncthreads();

    // --- gh = h @ W_hh : packed f32x2, 2 rows x (8 j as 4 pairs) x 3 gates ---
    u64 aR[2][4], aZ[2][4], aN[2][4];
    #pragma unroll
    for(int i=0;i<2;i++)
      #pragma unroll
      for(int l=0;l<4;l++){ aR[i][l]=0ull; aZ[i][l]=0ull; aN[i][l]=0ull; }

    #pragma unroll 4
    for (int k4=0;k4<16;k4++){
      float4 h0 = *(const float4*)&sh[(r0  )*64+k4*4];
      float4 h1 = *(const float4*)&sh[(r0+1)*64+k4*4];
      #pragma unroll
      for(int kk=0;kk<4;kk++){
        const float* wrow = &sW[(k4*4+kk)*192];
        ulonglong2 wrA = *(const ulonglong2*)&wrow[j0];
        ulonglong2 wrB = *(const ulonglong2*)&wrow[j0+4];
        ulonglong2 wzA = *(const ulonglong2*)&wrow[64+j0];
        ulonglong2 wzB = *(const ulonglong2*)&wrow[64+j0+4];
        ulonglong2 wnA = *(const ulonglong2*)&wrow[128+j0];
        ulonglong2 wnB = *(const ulonglong2*)&wrow[128+j0+4];
        float hv0 = (kk==0)?h0.x:(kk==1)?h0.y:(kk==2)?h0.z:h0.w;
        float hv1 = (kk==0)?h1.x:(kk==1)?h1.y:(kk==2)?h1.z:h1.w;
        u64 p0=pk2(hv0), p1=pk2(hv1);
        fma2(aR[0][0],p0,wrA.x); fma2(aR[0][1],p0,wrA.y); fma2(aR[0][2],p0,wrB.x); fma2(aR[0][3],p0,wrB.y);
        fma2(aZ[0][0],p0,wzA.x); fma2(aZ[0][1],p0,wzA.y); fma2(aZ[0][2],p0,wzB.x); fma2(aZ[0][3],p0,wzB.y);
        fma2(aN[0][0],p0,wnA.x); fma2(aN[0][1],p0,wnA.y); fma2(aN[0][2],p0,wnB.x); fma2(aN[0][3],p0,wnB.y);
        fma2(aR[1][0],p1,wrA.x); fma2(aR[1][1],p1,wrA.y); fma2(aR[1][2],p1,wrB.x); fma2(aR[1][3],p1,wrB.y);
        fma2(aZ[1][0],p1,wzA.x); fma2(aZ[1][1],p1,wzA.y); fma2(aZ[1][2],p1,wzB.x); fma2(aZ[1][3],p1,wzB.y);
        fma2(aN[1][0],p1,wnA.x); fma2(aN[1][1],p1,wnA.y); fma2(aN[1][2],p1,wnB.x); fma2(aN[1][3],p1,wnB.y);
      }
    }

    // --- gates + state update (scalar) ---
    float hnew[2][8];
    #pragma unroll
    for(int i=0;i<2;i++){
      const int r=r0+i;
      const float ea0=sEA0[r], ea1=sEA1[r], ew=sEW[r];
      #pragma unroll
      for(int l2=0;l2<4;l2++){
        float2 vR=up2(aR[i][l2]), vZ=up2(aZ[i][l2]), vN=up2(aN[i][l2]);
        #pragma unroll
        for(int hf=0;hf<2;hf++){
          const int j=j0+l2*2+hf;
          float gR=(hf==0)?vR.x:vR.y, gZ=(hf==0)?vZ.x:vZ.y, gN=(hf==0)?vN.x:vN.y;
          float giR = ea0*sWih[j]     + ea1*sWih[192+j] + ew*sWih[384+j] + sbih[j];
          float giZ = ea0*sWih[64+j]  + ea1*sWih[256+j] + ew*sWih[448+j] + sbih[64+j];
          float giN = ea0*sWih[128+j] + ea1*sWih[320+j] + ew*sWih[512+j] + sbih[128+j];
          float rg = __fdividef(1.f, 1.f+__expf(-(giR+gR+sbhh[j])));
          float zg = __fdividef(1.f, 1.f+__expf(-(giZ+gZ+sbhh[64+j])));
          float pre = giN + rg*(gN+sbhh[128+j]);
          float nn = 1.f - __fdividef(2.f, __expf(2.f*pre)+1.f);   // tanh, sat-safe
          float ho = sh[r*64+j];
          hnew[i][l2*2+hf] = nn + zg*(ho-nn);
        }
      }
    }
    __syncthreads();
    #pragma unroll
    for(int i=0;i<2;i++){
      *(float4*)&sh[(r0+i)*64+j0  ] = make_float4(hnew[i][0],hnew[i][1],hnew[i][2],hnew[i][3]);
      *(float4*)&sh[(r0+i)*64+j0+4] = make_float4(hnew[i][4],hnew[i][5],hnew[i][6],hnew[i][7]);
    }
    __syncthreads();

    // --- e_rep = relu(h_new @ W1 + b1) @ W2 + b2 : packed ---
    u64 am[2][4];
    #pragma unroll
    for(int i=0;i<2;i++)
      #pragma unroll
      for(int l=0;l<4;l++) am[i][l]=0ull;
    #pragma unroll 4
    for (int k4=0;k4<16;k4++){
      float4 h0 = *(const float4*)&sh[(r0  )*64+k4*4];
      float4 h1 = *(const float4*)&sh[(r0+1)*64+k4*4];
      #pragma unroll
      for(int kk=0;kk<4;kk++){
        const float* w1r = &sW1v[(k4*4+kk)*64];
        ulonglong2 wA = *(const ulonglong2*)&w1r[j0];
        ulonglong2 wB = *(const ulonglong2*)&w1r[j0+4];
        float hv0 = (kk==0)?h0.x:(kk==1)?h0.y:(kk==2)?h0.z:h0.w;
        float hv1 = (kk==0)?h1.x:(kk==1)?h1.y:(kk==2)?h1.z:h1.w;
        u64 p0=pk2(hv0), p1=pk2(hv1);
        fma2(am[0][0],p0,wA.x); fma2(am[0][1],p0,wA.y); fma2(am[0][2],p0,wB.x); fma2(am[0][3],p0,wB.y);
        fma2(am[1][0],p1,wA.x); fma2(am[1][1],p1,wA.y); fma2(am[1][2],p1,wB.x); fma2(am[1][3],p1,wB.y);
      }
    }
    float p[2];
    #pragma unroll
    for(int i=0;i<2;i++){
      float s=0.f;
      #pragma unroll
      for(int l2=0;l2<4;l2++){
        float2 v=up2(am[i][l2]);
        float a0=fmaxf(v.x+sb1[j0+l2*2  ],0.f);
        float a1=fmaxf(v.y+sb1[j0+l2*2+1],0.f);
        s += a0*sW2v[j0+l2*2] + a1*sW2v[j0+l2*2+1];
      }
      p[i]=s;
    }
    #pragma unroll
    for(int off=4;off;off>>=1){
      p[0]+=__shfl_down_sync(0xffffffffu,p[0],off,8);
      p[1]+=__shfl_down_sync(0xffffffffu,p[1],off,8);
    }
    if (jg==0){
      g_erep[t*BE + base + r0    ] = p[0]+b2v;
      g_erep[t*BE + base + r0 + 1] = p[1]+b2v;
    }
    __syncthreads();
  }
}

// ---------------- softmax rows of R + c_pred, streamed dense writes ----------------
__global__ void krow(const int* __restrict__ eidx, float* __restrict__ out)
{
  __shared__ float srow[8][Nn];
  const int wid = threadIdx.x>>5, lane=threadIdx.x&31;
  const int gid = blockIdx.x*8 + wid;     // == (b*Tt+t)*Nn + tgt
  const int tgt = gid % Nn;
  const int bt  = gid / Nn;
  const int t   = bt % Tt;
  const int b   = bt / Tt;
  const int rs  = g_rowptr[tgt];
  const int cnt = g_cnt[tgt];
  const float* er  = g_erep + (size_t)t*BE + (size_t)b*Ee;
  const float* hnb = g_hn + b*Nn;

  float vmax=0.f;  // empty slots contribute 0
  for (int i=lane;i<cnt;i+=32){ float v=er[g_colidx[rs+i]]; vmax=fmaxf(vmax,v); }
  #pragma unroll
  for(int off=16;off;off>>=1) vmax=fmaxf(vmax,__shfl_xor_sync(0xffffffffu,vmax,off));

  float se=0.f, shw=0.f, shf=0.f;
  for (int i=lane;i<cnt;i+=32){
    int e=g_colidx[rs+i];
    float v=er[e];
    float ex=__expf(v-vmax);
    float hv=hnb[eidx[e]];
    se+=ex; shw+=ex*hv; shf+=hv;
  }
  #pragma unroll
  for(int off=16;off;off>>=1){
    se +=__shfl_xor_sync(0xffffffffu,se ,off);
    shw+=__shfl_xor_sync(0xffffffffu,shw,off);
    shf+=__shfl_xor_sync(0xffffffffu,shf,off);
  }
  float ez  = __expf(-vmax);
  float inv = __fdividef(1.f, (float)(Nn-cnt)*ez + se);
  float defv= ez*inv;
  if (lane==0) out[gid] = (ez*(g_sumhn[b]-shf)+shw)*inv;   // c_pred

  float* row = srow[wid];
  for (int s=lane;s<Nn;s+=32) row[s]=defv;
  __syncwarp();
  for (int i=lane;i<cnt;i+=32){
    int e=g_colidx[rs+i];
    row[eidx[e]] = __expf(er[e]-vmax)*inv;
  }
  __syncwarp();
  float* dst = out + PRED_ELEMS + (size_t)gid*Nn;
  float4* d4=(float4*)dst; const float4* s4=(const float4*)row;
  for (int s=lane;s<Nn/4;s+=32) d4[s]=s4[s];
}

// ---------------- launch ----------------
extern "C" void kernel_launch(void* const* d_in, const int* in_sizes, int n_in,
                              void* d_out, int out_size){
  const float* pm25   =(const float*)d_in[0];
  const float* feature=(const float*)d_in[1];
  const int*   eidx   =(const int*)  d_in[2];
  const float* eattr  =(const float*)d_in[3];
  const float* wmean  =(const float*)d_in[4];
  const float* wstd   =(const float*)d_in[5];
  const float* W_ih   =(const float*)d_in[6];
  const float* W_hh   =(const float*)d_in[7];
  const float* b_ih   =(const float*)d_in[8];
  const float* b_hh   =(const float*)d_in[9];
  const float* W1     =(const float*)d_in[10];
  const float* b1     =(const float*)d_in[11];
  const float* W2     =(const float*)d_in[12];
  const float* b2     =(const float*)d_in[13];
  const float* W_node =(const float*)d_in[14];
  const float* b_node =(const float*)d_in[15];
  float* out=(float*)d_out;

  const int smem_bytes = 21888*4 + 64*4;   // 87808
  cudaFuncSetAttribute(kgru, cudaFuncAttributeMaxDynamicSharedMemorySize, smem_bytes);

  kstat <<<1,1024>>>(eattr);
  kcount<<<96,256>>>(eidx);
  kscan <<<1,1024>>>();
  kfill <<<96,256>>>(eidx);
  kfix  <<<3,256>>>(eidx);
  khn   <<<8,256>>>(pm25,W_node,b_node);
  kgru  <<<3072,256,smem_bytes>>>(feature,eidx,eattr,wmean,wstd,
                                  W_ih,W_hh,b_ih,b_hh,W1,b1,W2,b2);
  krow  <<<18432,256>>>(eidx,out);
}

// round 10
// speedup vs baseline: 4.6159x; 4.6159x over previous
#include <cuda_runtime.h>
#include <cuda_bf16.h>
#include <math.h>
#include <stdint.h>

#define Bb 8
#define Tt 24
#define Nn 768
#define Ee 24576
#define Hh 64
#define BE 196608              // B*E
#define PRED_ELEMS (Bb*Tt*Nn)  // 147456

// ---------------- device scratch (static, no allocs) ----------------
__device__ float g_stat[4];
__device__ float g_hn[Bb*Nn];
__device__ float g_sumhn[Bb];
__device__ int   g_cnt_raw[Nn];
__device__ int   g_rowptr[Nn+1];
__device__ int   g_cursor[Nn];
__device__ int   g_colidx[Ee];
__device__ int   g_cnt[Nn];
__device__ float g_erep[Tt*BE];      // 18.9 MB

// ---------------- SMEM map (f32/u32 units) ----------------
// 0..16383           : B-fragment images (u32), 256 frags x 64 u32
//   frag id: Whh (g,p,nt,kt) = g*64+p*32+nt*4+kt   (g=0r,1z,2n; p=0 hi,1 lo)
//            W1  (p,nt,kt)   = 192 + p*32+nt*4+kt
#define GI4_O  16384   // float4 per (g*64+j): {wih_f0, wih_f1, wih_f2, bias}
#define BHN_O  17152   // bhh n-part per j (64)
#define MB2_O  17216   // float2 per j: {b1, W2}
#define EA0_O  17344
#define EA1_O  17600
#define EW_O   17856
#define C3D_O  18112
#define DIR_O  18368
#define SRC_O  18624
#define SMEM_F32 18880
#define SMEM_SZ  (SMEM_F32*4)   // 75520 B

// m16n8k16 bf16 mma (sm_80+ baseline; works on sm_100 base target)
#define MMA(D,A,b0,b1) \
  asm("mma.sync.aligned.m16n8k16.row.col.f32.bf16.bf16.f32 " \
      "{%0,%1,%2,%3}, {%4,%5,%6,%7}, {%8,%9}, {%0,%1,%2,%3};" \
      : "+f"((D)[0]),"+f"((D)[1]),"+f"((D)[2]),"+f"((D)[3]) \
      : "r"((A)[0]),"r"((A)[1]),"r"((A)[2]),"r"((A)[3]), "r"(b0),"r"(b1))

__device__ __forceinline__ float ubfh(uint32_t v, int hf){
  return __bfloat162float(__ushort_as_bfloat16((unsigned short)(hf?(v>>16):(v&0xffff))));
}
__device__ __forceinline__ void pksplit(float x, float y, uint32_t& hi, uint32_t& lo){
  __nv_bfloat16 xh=__float2bfloat16(x), yh=__float2bfloat16(y);
  __nv_bfloat16 xl=__float2bfloat16(x-__bfloat162float(xh));
  __nv_bfloat16 yl=__float2bfloat16(y-__bfloat162float(yh));
  hi = (uint32_t)__bfloat16_as_ushort(xh) | ((uint32_t)__bfloat16_as_ushort(yh)<<16);
  lo = (uint32_t)__bfloat16_as_ushort(xl) | ((uint32_t)__bfloat16_as_ushort(yl)<<16);
}

// ---------------- prep kernels (proven) ----------------
__global__ void kstat(const float* __restrict__ eattr){
  __shared__ double red[1024];
  int tid = threadIdx.x;
  double s0=0,s1=0,q0=0,q1=0;
  for (int e=tid; e<Ee; e+=1024){
    double a=eattr[2*e], b=eattr[2*e+1];
    s0+=a; s1+=b; q0+=a*a; q1+=b*b;
  }
  double vals[4]={s0,s1,q0,q1};
  double out[4];
  for (int v=0; v<4; ++v){
    red[tid]=vals[v]; __syncthreads();
    for (int off=512; off; off>>=1){ if (tid<off) red[tid]+=red[tid+off]; __syncthreads(); }
    out[v]=red[0]; __syncthreads();
  }
  if (tid==0){
    double m0=out[0]/Ee, m1=out[1]/Ee;
    double v0=(out[2]-out[0]*out[0]/Ee)/(double)(Ee-1);
    double v1=(out[3]-out[1]*out[1]/Ee)/(double)(Ee-1);
    g_stat[0]=(float)m0; g_stat[1]=(float)m1;
    g_stat[2]=(float)(1.0/sqrt(v0)); g_stat[3]=(float)(1.0/sqrt(v1));
  }
  if (tid<Nn) g_cnt_raw[tid]=0;
}

__global__ void kcount(const int* __restrict__ eidx){
  int e = blockIdx.x*256+threadIdx.x;
  if (e<Ee) atomicAdd(&g_cnt_raw[eidx[Ee+e]],1);
}

__global__ void kscan(){
  __shared__ int a[Nn];
  int t=threadIdx.x;
  if (t<Nn) a[t]=g_cnt_raw[t];
  __syncthreads();
  for (int d=1; d<Nn; d<<=1){
    int v=0;
    if (t<Nn && t>=d) v=a[t-d];
    __syncthreads();
    if (t<Nn) a[t]+=v;
    __syncthreads();
  }
  if (t<Nn){ g_rowptr[t+1]=a[t]; g_cursor[t]=a[t]-g_cnt_raw[t]; }
  if (t==0) g_rowptr[0]=0;
}

__global__ void kfill(const int* __restrict__ eidx){
  int e = blockIdx.x*256+threadIdx.x;
  if (e<Ee){ int pos=atomicAdd(&g_cursor[eidx[Ee+e]],1); g_colidx[pos]=e; }
}

__global__ void kfix(const int* __restrict__ eidx){
  int t = blockIdx.x*256+threadIdx.x;
  if (t>=Nn) return;
  int rs=g_rowptr[t], re=g_rowptr[t+1];
  for (int i=rs+1;i<re;i++){
    int key=g_colidx[i]; int j=i-1;
    while(j>=rs && g_colidx[j]>key){ g_colidx[j+1]=g_colidx[j]; j--; }
    g_colidx[j+1]=key;
  }
  int w=rs;
  for (int i=rs;i<re;i++){
    int e=g_colidx[i]; int src=eidx[e];
    bool later=false;
    for (int j2=i+1;j2<re;j2++){ if (eidx[g_colidx[j2]]==src){later=true;break;} }
    if (!later) g_colidx[w++]=e;
  }
  g_cnt[t]=w-rs;
}

__global__ void khn(const float* __restrict__ pm25,
                    const float* __restrict__ Wn, const float* __restrict__ bn){
  __shared__ float red[256];
  int b=blockIdx.x, t=threadIdx.x;
  float w=Wn[0], bb=bn[0];
  float s=0.f;
  for (int n=t;n<Nn;n+=256){ float h=pm25[b*Nn+n]*w+bb; g_hn[b*Nn+n]=h; s+=h; }
  red[t]=s; __syncthreads();
  for(int off=128;off;off>>=1){ if(t<off) red[t]+=red[t+off]; __syncthreads(); }
  if(t==0) g_sumhn[b]=red[0];
}

// ---------------- main GRU+MLP: HMMA bf16 hi/lo, h register-resident ----------------
__global__ void __launch_bounds__(256,1) kgru(
    const float* __restrict__ feature, const int* __restrict__ eidx,
    const float* __restrict__ eattr,   const float* __restrict__ wmean,
    const float* __restrict__ wstd,    const float* __restrict__ W_ih,
    const float* __restrict__ W_hh,    const float* __restrict__ b_ih,
    const float* __restrict__ b_hh,    const float* __restrict__ W1,
    const float* __restrict__ b1,      const float* __restrict__ W2,
    const float* __restrict__ b2)
{
  extern __shared__ uint32_t su[];
  float* sf = (float*)su;

  const int tid=threadIdx.x, wid=tid>>5, lane=tid&31;
  const int gq=lane>>2, tig=lane&3;
  const int base=blockIdx.x*256, bIdx=base/Ee, e0=base%Ee;

  // ---- build B-fragment images (hi/lo split), exact mma register layout ----
  for (int idx=tid; idx<16384; idx+=256){
    int f=idx>>6, r6=idx&63, ln=r6>>1, reg=r6&1;
    int g2=ln>>2, t2=ln&3;
    float w0,w1;
    int p;
    if (f<192){
      int kt=f&3, nt=(f>>2)&7, g=f>>6; p=(f>>5)&1;
      int n = g*64 + nt*8 + g2;
      int k0 = kt*16 + t2*2 + reg*8;
      w0 = W_hh[k0*192+n]; w1 = W_hh[(k0+1)*192+n];
    } else {
      int f2=f-192, kt=f2&3, nt=(f2>>2)&7; p=(f2>>5)&1;
      int n = nt*8+g2;
      int k0 = kt*16 + t2*2 + reg*8;
      w0 = W1[k0*64+n]; w1 = W1[(k0+1)*64+n];
    }
    __nv_bfloat16 h0=__float2bfloat16(w0), h1=__float2bfloat16(w1);
    if (p){ h0=__float2bfloat16(w0-__bfloat162float(h0)); h1=__float2bfloat16(w1-__bfloat162float(h1)); }
    su[idx] = (uint32_t)__bfloat16_as_ushort(h0) | ((uint32_t)__bfloat16_as_ushort(h1)<<16);
  }
  // ---- gi coefficient tables ----
  if (tid<192){
    int g=tid>>6, j=tid&63;
    float bias = b_ih[g*64+j] + (g==2 ? 0.f : b_hh[g*64+j]);
    float4 cf = make_float4(W_ih[g*64+j], W_ih[192+g*64+j], W_ih[384+g*64+j], bias);
    *(float4*)&sf[GI4_O + (g*64+j)*4] = cf;
  }
  if (tid<64){
    sf[BHN_O+tid] = b_hh[128+tid];
    sf[MB2_O+tid*2]   = b1[tid];
    sf[MB2_O+tid*2+1] = W2[tid];
  }
  {
    int e=e0+tid;
    ((int*)su)[SRC_O+tid]=eidx[e];
    float dd=eattr[2*e], dr=eattr[2*e+1];
    sf[DIR_O+tid]=dr;
    sf[C3D_O+tid]=3.f/dd;
    sf[EA0_O+tid]=(dd-g_stat[0])*g_stat[2];
    sf[EA1_O+tid]=(dr-g_stat[1])*g_stat[3];
  }
  const float wm0=wmean[0], wm1=wmean[1], ws0=wstd[0], ws1=wstd[1];
  const float b2v=b2[0];
  __syncthreads();

  // per-thread row constants: ri = rb*2+ch -> row = wid*32 + rb*16 + ch*8 + gq
  float ea0v[4], ea1v[4];
  #pragma unroll
  for (int ri=0;ri<4;ri++){
    int row = wid*32 + (ri>>1)*16 + (ri&1)*8 + gq;
    ea0v[ri]=sf[EA0_O+row]; ea1v[ri]=sf[EA1_O+row];
  }

  // h state: A-fragments, bf16 hi/lo.  [rb][kt][reg]
  uint32_t Ah[2][4][4], Al[2][4][4];
  #pragma unroll
  for(int rb=0;rb<2;rb++)
    #pragma unroll
    for(int kt=0;kt<4;kt++)
      #pragma unroll
      for(int r=0;r<4;r++){ Ah[rb][kt][r]=0u; Al[rb][kt][r]=0u; }

  float accA[2][8][4], accB[2][8][4];

  // 3-pass hi/lo sweep over one gate/matrix: FHI/FLO are frag-id bases
#define SWEEP(ACC,FHI,FLO) do{ \
  _Pragma("unroll") \
  for(int kt=0;kt<4;kt++){ \
    _Pragma("unroll") \
    for(int nt=0;nt<8;nt++){ \
      uint2 bh = *(const uint2*)&su[(((FHI)+nt*4+kt)<<6) + (lane<<1)]; \
      uint2 bl = *(const uint2*)&su[(((FLO)+nt*4+kt)<<6) + (lane<<1)]; \
      MMA(ACC[0][nt], Ah[0][kt], bh.x, bh.y); \
      MMA(ACC[0][nt], Al[0][kt], bh.x, bh.y); \
      MMA(ACC[0][nt], Ah[0][kt], bl.x, bl.y); \
      MMA(ACC[1][nt], Ah[1][kt], bh.x, bh.y); \
      MMA(ACC[1][nt], Al[1][kt], bh.x, bh.y); \
      MMA(ACC[1][nt], Ah[1][kt], bl.x, bl.y); \
    } \
  } \
}while(0)

#define ZERO(ACC) do{ \
  _Pragma("unroll") for(int rb=0;rb<2;rb++) \
  _Pragma("unroll") for(int nt=0;nt<8;nt++) \
  _Pragma("unroll") for(int c=0;c<4;c++) (ACC)[rb][nt][c]=0.f; \
}while(0)

  for (int t=0;t<Tt;t++){
    __syncthreads();
    {
      int s = ((const int*)su)[SRC_O+tid];
      const float* fp = feature + ((size_t)(bIdx*25+1+t)*Nn + s)*4 + 2;
      float speed = fp[0]*ws0+wm0;
      float wdir  = fp[1]*ws1+wm1;
      sf[EW_O+tid] = fmaxf(sf[C3D_O+tid]*speed*cosf(sf[DIR_O+tid]-wdir),0.f);
    }
    __syncthreads();
    float ewv[4];
    #pragma unroll
    for (int ri=0;ri<4;ri++) ewv[ri]=sf[EW_O + wid*32 + (ri>>1)*16 + (ri&1)*8 + gq];

    // ---- gate R -> accA becomes r ----
    ZERO(accA);
    SWEEP(accA, 0, 32);
    #pragma unroll
    for(int nt=0;nt<8;nt++)
      #pragma unroll
      for(int par=0;par<2;par++){
        int j = nt*8 + tig*2 + par;
        float4 cf = *(const float4*)&sf[GI4_O + j*4];
        #pragma unroll
        for(int ri=0;ri<4;ri++){
          int rb=ri>>1, c=(ri&1)*2+par;
          float gi = ea0v[ri]*cf.x + ea1v[ri]*cf.y + ewv[ri]*cf.z + cf.w;
          accA[rb][nt][c] = __fdividef(1.f, 1.f+__expf(-(gi+accA[rb][nt][c])));
        }
      }
    // ---- gate N -> accB becomes n ----
    ZERO(accB);
    SWEEP(accB, 128, 160);
    #pragma unroll
    for(int nt=0;nt<8;nt++)
      #pragma unroll
      for(int par=0;par<2;par++){
        int j = nt*8 + tig*2 + par;
        float4 cf = *(const float4*)&sf[GI4_O + (128+j)*4];
        float bhn = sf[BHN_O+j];
        #pragma unroll
        for(int ri=0;ri<4;ri++){
          int rb=ri>>1, c=(ri&1)*2+par;
          float gi = ea0v[ri]*cf.x + ea1v[ri]*cf.y + ewv[ri]*cf.z + cf.w;
          float pre = gi + accA[rb][nt][c]*(accB[rb][nt][c]+bhn);
          accB[rb][nt][c] = 1.f - __fdividef(2.f, __expf(2.f*pre)+1.f);
        }
      }
    // ---- gate Z -> accA; h_new into accA ----
    ZERO(accA);
    SWEEP(accA, 64, 96);
    #pragma unroll
    for(int nt=0;nt<8;nt++)
      #pragma unroll
      for(int par=0;par<2;par++){
        int j = nt*8 + tig*2 + par;
        float4 cf = *(const float4*)&sf[GI4_O + (64+j)*4];
        #pragma unroll
        for(int ri=0;ri<4;ri++){
          int rb=ri>>1, c=(ri&1)*2+par;
          float gi = ea0v[ri]*cf.x + ea1v[ri]*cf.y + ewv[ri]*cf.z + cf.w;
          float z = __fdividef(1.f, 1.f+__expf(-(gi+accA[rb][nt][c])));
          int ridx = (nt&1)*2 + (c>>1);
          float hold = ubfh(Ah[rb][nt>>1][ridx], c&1) + ubfh(Al[rb][nt>>1][ridx], c&1);
          float n = accB[rb][nt][c];
          accA[rb][nt][c] = n + z*(hold-n);
        }
      }
    // ---- pack h_new -> A fragments ----
    #pragma unroll
    for(int rb=0;rb<2;rb++)
      #pragma unroll
      for(int kt=0;kt<4;kt++){
        pksplit(accA[rb][2*kt][0],  accA[rb][2*kt][1],  Ah[rb][kt][0], Al[rb][kt][0]);
        pksplit(accA[rb][2*kt][2],  accA[rb][2*kt][3],  Ah[rb][kt][1], Al[rb][kt][1]);
        pksplit(accA[rb][2*kt+1][0],accA[rb][2*kt+1][1],Ah[rb][kt][2], Al[rb][kt][2]);
        pksplit(accA[rb][2*kt+1][2],accA[rb][2*kt+1][3],Ah[rb][kt][3], Al[rb][kt][3]);
      }
    // ---- MLP: accB = h_new @ W1 ----
    ZERO(accB);
    SWEEP(accB, 192, 224);
    float p[4] = {0.f,0.f,0.f,0.f};
    #pragma unroll
    for(int nt=0;nt<8;nt++)
      #pragma unroll
      for(int par=0;par<2;par++){
        int j = nt*8 + tig*2 + par;
        float bb1 = sf[MB2_O+j*2], ww2 = sf[MB2_O+j*2+1];
        #pragma unroll
        for(int ri=0;ri<4;ri++){
          int rb=ri>>1, c=(ri&1)*2+par;
          p[ri] += fmaxf(accB[rb][nt][c]+bb1,0.f)*ww2;
        }
      }
    #pragma unroll
    for(int ri=0;ri<4;ri++){
      p[ri] += __shfl_xor_sync(0xffffffffu,p[ri],1);
      p[ri] += __shfl_xor_sync(0xffffffffu,p[ri],2);
    }
    if (tig==0){
      #pragma unroll
      for(int ri=0;ri<4;ri++){
        int row = wid*32 + (ri>>1)*16 + (ri&1)*8 + gq;
        g_erep[t*BE + base + row] = p[ri]+b2v;
      }
    }
  }
#undef SWEEP
#undef ZERO
}

// ---------------- softmax rows of R + c_pred (proven) ----------------
__global__ void krow(const int* __restrict__ eidx, float* __restrict__ out)
{
  __shared__ float srow[8][Nn];
  const int wid = threadIdx.x>>5, lane=threadIdx.x&31;
  const int gid = blockIdx.x*8 + wid;
  const int tgt = gid % Nn;
  const int bt  = gid / Nn;
  const int t   = bt % Tt;
  const int b   = bt / Tt;
  const int rs  = g_rowptr[tgt];
  const int cnt = g_cnt[tgt];
  const float* er  = g_erep + (size_t)t*BE + (size_t)b*Ee;
  const float* hnb = g_hn + b*Nn;

  float vmax=0.f;
  for (int i=lane;i<cnt;i+=32){ float v=er[g_colidx[rs+i]]; vmax=fmaxf(vmax,v); }
  #pragma unroll
  for(int off=16;off;off>>=1) vmax=fmaxf(vmax,__shfl_xor_sync(0xffffffffu,vmax,off));

  float se=0.f, shw=0.f, shf=0.f;
  for (int i=lane;i<cnt;i+=32){
    int e=g_colidx[rs+i];
    float v=er[e];
    float ex=__expf(v-vmax);
    float hv=hnb[eidx[e]];
    se+=ex; shw+=ex*hv; shf+=hv;
  }
  #pragma unroll
  for(int off=16;off;off>>=1){
    se +=__shfl_xor_sync(0xffffffffu,se ,off);
    shw+=__shfl_xor_sync(0xffffffffu,shw,off);
    shf+=__shfl_xor_sync(0xffffffffu,shf,off);
  }
  float ez  = __expf(-vmax);
  float inv = __fdividef(1.f, (float)(Nn-cnt)*ez + se);
  float defv= ez*inv;
  if (lane==0) out[gid] = (ez*(g_sumhn[b]-shf)+shw)*inv;

  float* row = srow[wid];
  for (int s=lane;s<Nn;s+=32) row[s]=defv;
  __syncwarp();
  for (int i=lane;i<cnt;i+=32){
    int e=g_colidx[rs+i];
    row[eidx[e]] = __expf(er[e]-vmax)*inv;
  }
  __syncwarp();
  float* dst = out + PRED_ELEMS + (size_t)gid*Nn;
  float4* d4=(float4*)dst; const float4* s4=(const float4*)row;
  for (int s=lane;s<Nn/4;s+=32) d4[s]=s4[s];
}

// ---------------- launch ----------------
extern "C" void kernel_launch(void* const* d_in, const int* in_sizes, int n_in,
                              void* d_out, int out_size){
  const float* pm25   =(const float*)d_in[0];
  const float* feature=(const float*)d_in[1];
  const int*   eidx   =(const int*)  d_in[2];
  const float* eattr  =(const float*)d_in[3];
  const float* wmean  =(const float*)d_in[4];
  const float* wstd   =(const float*)d_in[5];
  const float* W_ih   =(const float*)d_in[6];
  const float* W_hh   =(const float*)d_in[7];
  const float* b_ih   =(const float*)d_in[8];
  const float* b_hh   =(const float*)d_in[9];
  const float* W1     =(const float*)d_in[10];
  const float* b1     =(const float*)d_in[11];
  const float* W2     =(const float*)d_in[12];
  const float* b2     =(const float*)d_in[13];
  const float* W_node =(const float*)d_in[14];
  const float* b_node =(const float*)d_in[15];
  float* out=(float*)d_out;

  cudaFuncSetAttribute(kgru, cudaFuncAttributeMaxDynamicSharedMemorySize, SMEM_SZ);

  kstat <<<1,1024>>>(eattr);
  kcount<<<96,256>>>(eidx);
  kscan <<<1,1024>>>();
  kfill <<<96,256>>>(eidx);
  kfix  <<<3,256>>>(eidx);
  khn   <<<8,256>>>(pm25,W_node,b_node);
  kgru  <<<768,256,SMEM_SZ>>>(feature,eidx,eattr,wmean,wstd,
                              W_ih,W_hh,b_ih,b_hh,W1,b1,W2,b2);
  krow  <<<18432,256>>>(eidx,out);
}

// round 11
// speedup vs baseline: 5.3400x; 1.1569x over previous
#include <cuda_runtime.h>
#include <cuda_bf16.h>
#include <math.h>
#include <stdint.h>

#define Bb 8
#define Tt 24
#define Nn 768
#define Ee 24576
#define Hh 64
#define BE 196608              // B*E
#define PRED_ELEMS (Bb*Tt*Nn)  // 147456

// ---------------- device scratch (static, no allocs) ----------------
__device__ float g_stat[4];
__device__ float g_hn[Bb*Nn];
__device__ float g_sumhn[Bb];
__device__ int   g_cnt_raw[Nn];
__device__ int   g_rowptr[Nn+1];
__device__ int   g_cursor[Nn];
__device__ int   g_colidx[Ee];
__device__ int   g_cnt[Nn];
__device__ float g_erep[Tt*BE];      // 18.9 MB

// ---------------- SMEM map (f32/u32 units) ----------------
#define GI4_O  16384   // float4 per (g*64+j): {wih_f0, wih_f1, wih_f2, bias}
#define BHN_O  17152   // bhh n-part per j (64)
#define MB2_O  17216   // float2 per j: {b1, W2}
#define EA0_O  17344
#define EA1_O  17600
#define EW_O   17856
#define C3D_O  18112
#define DIR_O  18368
#define SRC_O  18624
#define SMEM_F32 18880
#define SMEM_SZ  (SMEM_F32*4)   // 75520 B

// m16n8k16 bf16 mma (sm_80+ baseline)
#define MMA(D,A,b0,b1) \
  asm("mma.sync.aligned.m16n8k16.row.col.f32.bf16.bf16.f32 " \
      "{%0,%1,%2,%3}, {%4,%5,%6,%7}, {%8,%9}, {%0,%1,%2,%3};" \
      : "+f"((D)[0]),"+f"((D)[1]),"+f"((D)[2]),"+f"((D)[3]) \
      : "r"((A)[0]),"r"((A)[1]),"r"((A)[2]),"r"((A)[3]), "r"(b0),"r"(b1))

__device__ __forceinline__ float tanhfast(float x){
  float y; asm("tanh.approx.f32 %0,%1;":"=f"(y):"f"(x)); return y;
}
__device__ __forceinline__ float sigfast(float x){
  return 0.5f*tanhfast(0.5f*x)+0.5f;
}
__device__ __forceinline__ float ubfh(uint32_t v, int hf){
  return __bfloat162float(__ushort_as_bfloat16((unsigned short)(hf?(v>>16):(v&0xffff))));
}
__device__ __forceinline__ uint32_t pk_bf2(float x, float y){  // {lo16=x, hi16=y}
  uint32_t r; asm("cvt.rn.bf16x2.f32 %0, %1, %2;":"=r"(r):"f"(y),"f"(x)); return r;
}
__device__ __forceinline__ void pksplit(float x, float y, uint32_t& hi, uint32_t& lo){
  hi = pk_bf2(x,y);
  float xr = x - ubfh(hi,0);
  float yr = y - ubfh(hi,1);
  lo = pk_bf2(xr,yr);
}

// ---------------- prep kernels (proven) ----------------
__global__ void kstat(const float* __restrict__ eattr){
  __shared__ double red[1024];
  int tid = threadIdx.x;
  double s0=0,s1=0,q0=0,q1=0;
  for (int e=tid; e<Ee; e+=1024){
    double a=eattr[2*e], b=eattr[2*e+1];
    s0+=a; s1+=b; q0+=a*a; q1+=b*b;
  }
  double vals[4]={s0,s1,q0,q1};
  double out[4];
  for (int v=0; v<4; ++v){
    red[tid]=vals[v]; __syncthreads();
    for (int off=512; off; off>>=1){ if (tid<off) red[tid]+=red[tid+off]; __syncthreads(); }
    out[v]=red[0]; __syncthreads();
  }
  if (tid==0){
    double m0=out[0]/Ee, m1=out[1]/Ee;
    double v0=(out[2]-out[0]*out[0]/Ee)/(double)(Ee-1);
    double v1=(out[3]-out[1]*out[1]/Ee)/(double)(Ee-1);
    g_stat[0]=(float)m0; g_stat[1]=(float)m1;
    g_stat[2]=(float)(1.0/sqrt(v0)); g_stat[3]=(float)(1.0/sqrt(v1));
  }
  if (tid<Nn) g_cnt_raw[tid]=0;
}

__global__ void kcount(const int* __restrict__ eidx){
  int e = blockIdx.x*256+threadIdx.x;
  if (e<Ee) atomicAdd(&g_cnt_raw[eidx[Ee+e]],1);
}

__global__ void kscan(){
  __shared__ int a[Nn];
  int t=threadIdx.x;
  if (t<Nn) a[t]=g_cnt_raw[t];
  __syncthreads();
  for (int d=1; d<Nn; d<<=1){
    int v=0;
    if (t<Nn && t>=d) v=a[t-d];
    __syncthreads();
    if (t<Nn) a[t]+=v;
    __syncthreads();
  }
  if (t<Nn){ g_rowptr[t+1]=a[t]; g_cursor[t]=a[t]-g_cnt_raw[t]; }
  if (t==0) g_rowptr[0]=0;
}

__global__ void kfill(const int* __restrict__ eidx){
  int e = blockIdx.x*256+threadIdx.x;
  if (e<Ee){ int pos=atomicAdd(&g_cursor[eidx[Ee+e]],1); g_colidx[pos]=e; }
}

__global__ void kfix(const int* __restrict__ eidx){
  int t = blockIdx.x*256+threadIdx.x;
  if (t>=Nn) return;
  int rs=g_rowptr[t], re=g_rowptr[t+1];
  for (int i=rs+1;i<re;i++){
    int key=g_colidx[i]; int j=i-1;
    while(j>=rs && g_colidx[j]>key){ g_colidx[j+1]=g_colidx[j]; j--; }
    g_colidx[j+1]=key;
  }
  int w=rs;
  for (int i=rs;i<re;i++){
    int e=g_colidx[i]; int src=eidx[e];
    bool later=false;
    for (int j2=i+1;j2<re;j2++){ if (eidx[g_colidx[j2]]==src){later=true;break;} }
    if (!later) g_colidx[w++]=e;
  }
  g_cnt[t]=w-rs;
}

__global__ void khn(const float* __restrict__ pm25,
                    const float* __restrict__ Wn, const float* __restrict__ bn){
  __shared__ float red[256];
  int b=blockIdx.x, t=threadIdx.x;
  float w=Wn[0], bb=bn[0];
  float s=0.f;
  for (int n=t;n<Nn;n+=256){ float h=pm25[b*Nn+n]*w+bb; g_hn[b*Nn+n]=h; s+=h; }
  red[t]=s; __syncthreads();
  for(int off=128;off;off>>=1){ if(t<off) red[t]+=red[t+off]; __syncthreads(); }
  if(t==0) g_sumhn[b]=red[0];
}

// ---------------- main GRU+MLP: HMMA bf16 hi/lo, h register-resident ----------------
__global__ void __launch_bounds__(256,1) kgru(
    const float* __restrict__ feature, const int* __restrict__ eidx,
    const float* __restrict__ eattr,   const float* __restrict__ wmean,
    const float* __restrict__ wstd,    const float* __restrict__ W_ih,
    const float* __restrict__ W_hh,    const float* __restrict__ b_ih,
    const float* __restrict__ b_hh,    const float* __restrict__ W1,
    const float* __restrict__ b1,      const float* __restrict__ W2,
    const float* __restrict__ b2)
{
  extern __shared__ uint32_t su[];
  float* sf = (float*)su;

  const int tid=threadIdx.x, wid=tid>>5, lane=tid&31;
  const int gq=lane>>2, tig=lane&3;
  const int base=blockIdx.x*256, bIdx=base/Ee, e0=base%Ee;

  // ---- build B-fragment images (hi/lo split), exact mma register layout ----
  for (int idx=tid; idx<16384; idx+=256){
    int f=idx>>6, r6=idx&63, ln=r6>>1, reg=r6&1;
    int g2=ln>>2, t2=ln&3;
    float w0,w1;
    int p;
    if (f<192){
      int kt=f&3, nt=(f>>2)&7, g=f>>6; p=(f>>5)&1;
      int n = g*64 + nt*8 + g2;
      int k0 = kt*16 + t2*2 + reg*8;
      w0 = W_hh[k0*192+n]; w1 = W_hh[(k0+1)*192+n];
    } else {
      int f2=f-192, kt=f2&3, nt=(f2>>2)&7; p=(f2>>5)&1;
      int n = nt*8+g2;
      int k0 = kt*16 + t2*2 + reg*8;
      w0 = W1[k0*64+n]; w1 = W1[(k0+1)*64+n];
    }
    __nv_bfloat16 h0=__float2bfloat16(w0), h1=__float2bfloat16(w1);
    if (p){ h0=__float2bfloat16(w0-__bfloat162float(h0)); h1=__float2bfloat16(w1-__bfloat162float(h1)); }
    su[idx] = (uint32_t)__bfloat16_as_ushort(h0) | ((uint32_t)__bfloat16_as_ushort(h1)<<16);
  }
  // ---- gi coefficient tables ----
  if (tid<192){
    int g=tid>>6, j=tid&63;
    float bias = b_ih[g*64+j] + (g==2 ? 0.f : b_hh[g*64+j]);
    float4 cf = make_float4(W_ih[g*64+j], W_ih[192+g*64+j], W_ih[384+g*64+j], bias);
    *(float4*)&sf[GI4_O + (g*64+j)*4] = cf;
  }
  if (tid<64){
    sf[BHN_O+tid] = b_hh[128+tid];
    sf[MB2_O+tid*2]   = b1[tid];
    sf[MB2_O+tid*2+1] = W2[tid];
  }
  {
    int e=e0+tid;
    ((int*)su)[SRC_O+tid]=eidx[e];
    float dd=eattr[2*e], dr=eattr[2*e+1];
    sf[DIR_O+tid]=dr;
    sf[C3D_O+tid]=3.f/dd;
    sf[EA0_O+tid]=(dd-g_stat[0])*g_stat[2];
    sf[EA1_O+tid]=(dr-g_stat[1])*g_stat[3];
  }
  const float wm0=wmean[0], wm1=wmean[1], ws0=wstd[0], ws1=wstd[1];
  const float b2v=b2[0];
  __syncthreads();

  float ea0v[4], ea1v[4];
  #pragma unroll
  for (int ri=0;ri<4;ri++){
    int row = wid*32 + (ri>>1)*16 + (ri&1)*8 + gq;
    ea0v[ri]=sf[EA0_O+row]; ea1v[ri]=sf[EA1_O+row];
  }

  uint32_t Ah[2][4][4], Al[2][4][4];
  #pragma unroll
  for(int rb=0;rb<2;rb++)
    #pragma unroll
    for(int kt=0;kt<4;kt++)
      #pragma unroll
      for(int r=0;r<4;r++){ Ah[rb][kt][r]=0u; Al[rb][kt][r]=0u; }

  float accA[2][8][4], accB[2][8][4];

#define SWEEP(ACC,FHI,FLO) do{ \
  _Pragma("unroll") \
  for(int kt=0;kt<4;kt++){ \
    _Pragma("unroll") \
    for(int nt=0;nt<8;nt++){ \
      uint2 bh = *(const uint2*)&su[(((FHI)+nt*4+kt)<<6) + (lane<<1)]; \
      uint2 bl = *(const uint2*)&su[(((FLO)+nt*4+kt)<<6) + (lane<<1)]; \
      MMA(ACC[0][nt], Ah[0][kt], bh.x, bh.y); \
      MMA(ACC[0][nt], Al[0][kt], bh.x, bh.y); \
      MMA(ACC[0][nt], Ah[0][kt], bl.x, bl.y); \
      MMA(ACC[1][nt], Ah[1][kt], bh.x, bh.y); \
      MMA(ACC[1][nt], Al[1][kt], bh.x, bh.y); \
      MMA(ACC[1][nt], Ah[1][kt], bl.x, bl.y); \
    } \
  } \
}while(0)

#define ZERO(ACC) do{ \
  _Pragma("unroll") for(int rb=0;rb<2;rb++) \
  _Pragma("unroll") for(int nt=0;nt<8;nt++) \
  _Pragma("unroll") for(int c=0;c<4;c++) (ACC)[rb][nt][c]=0.f; \
}while(0)

  for (int t=0;t<Tt;t++){
    __syncthreads();
    {
      int s = ((const int*)su)[SRC_O+tid];
      const float* fp = feature + ((size_t)(bIdx*25+1+t)*Nn + s)*4 + 2;
      float speed = fp[0]*ws0+wm0;
      float wdir  = fp[1]*ws1+wm1;
      sf[EW_O+tid] = fmaxf(sf[C3D_O+tid]*speed*cosf(sf[DIR_O+tid]-wdir),0.f);
    }
    __syncthreads();
    float ewv[4];
    #pragma unroll
    for (int ri=0;ri<4;ri++) ewv[ri]=sf[EW_O + wid*32 + (ri>>1)*16 + (ri&1)*8 + gq];

    // ---- gate R -> accA becomes r ----
    ZERO(accA);
    SWEEP(accA, 0, 32);
    #pragma unroll
    for(int nt=0;nt<8;nt++)
      #pragma unroll
      for(int par=0;par<2;par++){
        int j = nt*8 + tig*2 + par;
        float4 cf = *(const float4*)&sf[GI4_O + j*4];
        #pragma unroll
        for(int ri=0;ri<4;ri++){
          int rb=ri>>1, c=(ri&1)*2+par;
          float gi = ea0v[ri]*cf.x + ea1v[ri]*cf.y + ewv[ri]*cf.z + cf.w;
          accA[rb][nt][c] = sigfast(gi+accA[rb][nt][c]);
        }
      }
    // ---- gate N -> accB becomes n ----
    ZERO(accB);
    SWEEP(accB, 128, 160);
    #pragma unroll
    for(int nt=0;nt<8;nt++)
      #pragma unroll
      for(int par=0;par<2;par++){
        int j = nt*8 + tig*2 + par;
        float4 cf = *(const float4*)&sf[GI4_O + (128+j)*4];
        float bhn = sf[BHN_O+j];
        #pragma unroll
        for(int ri=0;ri<4;ri++){
          int rb=ri>>1, c=(ri&1)*2+par;
          float gi = ea0v[ri]*cf.x + ea1v[ri]*cf.y + ewv[ri]*cf.z + cf.w;
          float pre = gi + accA[rb][nt][c]*(accB[rb][nt][c]+bhn);
          accB[rb][nt][c] = tanhfast(pre);
        }
      }
    // ---- gate Z -> accA; h_new into accA ----
    ZERO(accA);
    SWEEP(accA, 64, 96);
    #pragma unroll
    for(int nt=0;nt<8;nt++)
      #pragma unroll
      for(int par=0;par<2;par++){
        int j = nt*8 + tig*2 + par;
        float4 cf = *(const float4*)&sf[GI4_O + (64+j)*4];
        #pragma unroll
        for(int ri=0;ri<4;ri++){
          int rb=ri>>1, c=(ri&1)*2+par;
          float gi = ea0v[ri]*cf.x + ea1v[ri]*cf.y + ewv[ri]*cf.z + cf.w;
          float z = sigfast(gi+accA[rb][nt][c]);
          int ridx = (nt&1)*2 + (c>>1);
          float hold = ubfh(Ah[rb][nt>>1][ridx], c&1) + ubfh(Al[rb][nt>>1][ridx], c&1);
          float n = accB[rb][nt][c];
          accA[rb][nt][c] = n + z*(hold-n);
        }
      }
    // ---- pack h_new -> A fragments ----
    #pragma unroll
    for(int rb=0;rb<2;rb++)
      #pragma unroll
      for(int kt=0;kt<4;kt++){
        pksplit(accA[rb][2*kt][0],  accA[rb][2*kt][1],  Ah[rb][kt][0], Al[rb][kt][0]);
        pksplit(accA[rb][2*kt][2],  accA[rb][2*kt][3],  Ah[rb][kt][1], Al[rb][kt][1]);
        pksplit(accA[rb][2*kt+1][0],accA[rb][2*kt+1][1],Ah[rb][kt][2], Al[rb][kt][2]);
        pksplit(accA[rb][2*kt+1][2],accA[rb][2*kt+1][3],Ah[rb][kt][3], Al[rb][kt][3]);
      }
    // ---- MLP: accB = h_new @ W1 ----
    ZERO(accB);
    SWEEP(accB, 192, 224);
    float p[4] = {0.f,0.f,0.f,0.f};
    #pragma unroll
    for(int nt=0;nt<8;nt++)
      #pragma unroll
      for(int par=0;par<2;par++){
        int j = nt*8 + tig*2 + par;
        float bb1 = sf[MB2_O+j*2], ww2 = sf[MB2_O+j*2+1];
        #pragma unroll
        for(int ri=0;ri<4;ri++){
          int rb=ri>>1, c=(ri&1)*2+par;
          p[ri] += fmaxf(accB[rb][nt][c]+bb1,0.f)*ww2;
        }
      }
    #pragma unroll
    for(int ri=0;ri<4;ri++){
      p[ri] += __shfl_xor_sync(0xffffffffu,p[ri],1);
      p[ri] += __shfl_xor_sync(0xffffffffu,p[ri],2);
    }
    if (tig==0){
      #pragma unroll
      for(int ri=0;ri<4;ri++){
        int row = wid*32 + (ri>>1)*16 + (ri&1)*8 + gq;
        g_erep[t*BE + base + row] = p[ri]+b2v;
      }
    }
  }
#undef SWEEP
#undef ZERO
}

// ---------------- softmax rows of R + c_pred (proven) ----------------
__global__ void krow(const int* __restrict__ eidx, float* __restrict__ out)
{
  __shared__ float srow[8][Nn];
  const int wid = threadIdx.x>>5, lane=threadIdx.x&31;
  const int gid = blockIdx.x*8 + wid;
  const int tgt = gid % Nn;
  const int bt  = gid / Nn;
  const int t   = bt % Tt;
  const int b   = bt / Tt;
  const int rs  = g_rowptr[tgt];
  const int cnt = g_cnt[tgt];
  const float* er  = g_erep + (size_t)t*BE + (size_t)b*Ee;
  const float* hnb = g_hn + b*Nn;

  float vmax=0.f;
  for (int i=lane;i<cnt;i+=32){ float v=er[g_colidx[rs+i]]; vmax=fmaxf(vmax,v); }
  #pragma unroll
  for(int off=16;off;off>>=1) vmax=fmaxf(vmax,__shfl_xor_sync(0xffffffffu,vmax,off));

  float se=0.f, shw=0.f, shf=0.f;
  for (int i=lane;i<cnt;i+=32){
    int e=g_colidx[rs+i];
    float v=er[e];
    float ex=__expf(v-vmax);
    float hv=hnb[eidx[e]];
    se+=ex; shw+=ex*hv; shf+=hv;
  }
  #pragma unroll
  for(int off=16;off;off>>=1){
    se +=__shfl_xor_sync(0xffffffffu,se ,off);
    shw+=__shfl_xor_sync(0xffffffffu,shw,off);
    shf+=__shfl_xor_sync(0xffffffffu,shf,off);
  }
  float ez  = __expf(-vmax);
  float inv = __fdividef(1.f, (float)(Nn-cnt)*ez + se);
  float defv= ez*inv;
  if (lane==0) out[gid] = (ez*(g_sumhn[b]-shf)+shw)*inv;

  float* row = srow[wid];
  for (int s=lane;s<Nn;s+=32) row[s]=defv;
  __syncwarp();
  for (int i=lane;i<cnt;i+=32){
    int e=g_colidx[rs+i];
    row[eidx[e]] = __expf(er[e]-vmax)*inv;
  }
  __syncwarp();
  float* dst = out + PRED_ELEMS + (size_t)gid*Nn;
  float4* d4=(float4*)dst; const float4* s4=(const float4*)row;
  for (int s=lane;s<Nn/4;s+=32) d4[s]=s4[s];
}

// ---------------- launch (kgru moved to 6th launch so ncu -s5 profiles it) ----------------
extern "C" void kernel_launch(void* const* d_in, const int* in_sizes, int n_in,
                              void* d_out, int out_size){
  const float* pm25   =(const float*)d_in[0];
  const float* feature=(const float*)d_in[1];
  const int*   eidx   =(const int*)  d_in[2];
  const float* eattr  =(const float*)d_in[3];
  const float* wmean  =(const float*)d_in[4];
  const float* wstd   =(const float*)d_in[5];
  const float* W_ih   =(const float*)d_in[6];
  const float* W_hh   =(const float*)d_in[7];
  const float* b_ih   =(const float*)d_in[8];
  const float* b_hh   =(const float*)d_in[9];
  const float* W1     =(const float*)d_in[10];
  const float* b1     =(const float*)d_in[11];
  const float* W2     =(const float*)d_in[12];
  const float* b2     =(const float*)d_in[13];
  const float* W_node =(const float*)d_in[14];
  const float* b_node =(const float*)d_in[15];
  float* out=(float*)d_out;

  cudaFuncSetAttribute(kgru, cudaFuncAttributeMaxDynamicSharedMemorySize, SMEM_SZ);

  kstat <<<1,1024>>>(eattr);
  kcount<<<96,256>>>(eidx);
  kscan <<<1,1024>>>();
  kfill <<<96,256>>>(eidx);
  kfix  <<<3,256>>>(eidx);
  kgru  <<<768,256,SMEM_SZ>>>(feature,eidx,eattr,wmean,wstd,
                              W_ih,W_hh,b_ih,b_hh,W1,b1,W2,b2);
  khn   <<<8,256>>>(pm25,W_node,b_node);
  krow  <<<18432,256>>>(eidx,out);
}

// round 14
// speedup vs baseline: 6.6768x; 1.2503x over previous
#include <cuda_runtime.h>
#include <cuda_bf16.h>
#include <math.h>
#include <stdint.h>

#define Bb 8
#define Tt 24
#define Nn 768
#define Ee 24576
#define Hh 64
#define BE 196608              // B*E
#define PRED_ELEMS (Bb*Tt*Nn)  // 147456

// ---------------- device scratch (static, no allocs) ----------------
__device__ float g_stat[4];
__device__ float g_hn[Bb*Nn];
__device__ float g_sumhn[Bb];
__device__ int   g_cnt_raw[Nn];
__device__ int   g_rowptr[Nn+1];
__device__ int   g_cursor[Nn];
__device__ int   g_colidx[Ee];
__device__ int   g_cnt[Nn];
__device__ float g_erep[Tt*BE];      // 18.9 MB

// ---------------- SMEM map (f32/u32 units) ----------------
// 0..8191 : B-fragment images (u32), 128 frags x 64 u32 (bf16-hi only)
//   frag id: Whh (g,nt,kt) = g*32+nt*4+kt  (g=0r,1z,2n) ; W1 = 96+nt*4+kt
#define GI4_O  8192    // float4 per (g*64+j): {wih_f0, wih_f1, wih_f2, bias}
#define BHN_O  8960    // bhh n-part per j (64)
#define MB2_O  9024    // float2 per j: {b1, W2}
#define EA0_O  9152
#define EA1_O  9408
#define EW_O   9664
#define C3D_O  9920
#define DIR_O  10176
#define SRC_O  10432
#define SMEM_F32 10688
#define SMEM_SZ  (SMEM_F32*4)   // 42752 B

// m16n8k16 bf16 mma (sm_80+ baseline)
#define MMA(D,A,b0,b1) \
  asm("mma.sync.aligned.m16n8k16.row.col.f32.bf16.bf16.f32 " \
      "{%0,%1,%2,%3}, {%4,%5,%6,%7}, {%8,%9}, {%0,%1,%2,%3};" \
      : "+f"((D)[0]),"+f"((D)[1]),"+f"((D)[2]),"+f"((D)[3]) \
      : "r"((A)[0]),"r"((A)[1]),"r"((A)[2]),"r"((A)[3]), "r"(b0),"r"(b1))

__device__ __forceinline__ float tanhfast(float x){
  float y; asm("tanh.approx.f32 %0,%1;":"=f"(y):"f"(x)); return y;
}
__device__ __forceinline__ float sigfast(float x){
  return 0.5f*tanhfast(0.5f*x)+0.5f;
}
__device__ __forceinline__ float ubfh(uint32_t v, int hf){
  return __bfloat162float(__ushort_as_bfloat16((unsigned short)(hf?(v>>16):(v&0xffff))));
}
__device__ __forceinline__ uint32_t pk_bf2(float x, float y){  // {lo16=x, hi16=y}
  uint32_t r; asm("cvt.rn.bf16x2.f32 %0, %1, %2;":"=r"(r):"f"(y),"f"(x)); return r;
}
__device__ __forceinline__ void pksplit(float x, float y, uint32_t& hi, uint32_t& lo){
  hi = pk_bf2(x,y);
  float xr = x - ubfh(hi,0);
  float yr = y - ubfh(hi,1);
  lo = pk_bf2(xr,yr);
}

// ---------------- prep kernels (proven) ----------------
__global__ void kstat(const float* __restrict__ eattr){
  __shared__ double red[1024];
  int tid = threadIdx.x;
  double s0=0,s1=0,q0=0,q1=0;
  for (int e=tid; e<Ee; e+=1024){
    double a=eattr[2*e], b=eattr[2*e+1];
    s0+=a; s1+=b; q0+=a*a; q1+=b*b;
  }
  double vals[4]={s0,s1,q0,q1};
  double out[4];
  for (int v=0; v<4; ++v){
    red[tid]=vals[v]; __syncthreads();
    for (int off=512; off; off>>=1){ if (tid<off) red[tid]+=red[tid+off]; __syncthreads(); }
    out[v]=red[0]; __syncthreads();
  }
  if (tid==0){
    double m0=out[0]/Ee, m1=out[1]/Ee;
    double v0=(out[2]-out[0]*out[0]/Ee)/(double)(Ee-1);
    double v1=(out[3]-out[1]*out[1]/Ee)/(double)(Ee-1);
    g_stat[0]=(float)m0; g_stat[1]=(float)m1;
    g_stat[2]=(float)(1.0/sqrt(v0)); g_stat[3]=(float)(1.0/sqrt(v1));
  }
  if (tid<Nn) g_cnt_raw[tid]=0;
}

__global__ void kcount(const int* __restrict__ eidx){
  int e = blockIdx.x*256+threadIdx.x;
  if (e<Ee) atomicAdd(&g_cnt_raw[eidx[Ee+e]],1);
}

__global__ void kscan(){
  __shared__ int a[Nn];
  int t=threadIdx.x;
  if (t<Nn) a[t]=g_cnt_raw[t];
  __syncthreads();
  for (int d=1; d<Nn; d<<=1){
    int v=0;
    if (t<Nn && t>=d) v=a[t-d];
    __syncthreads();
    if (t<Nn) a[t]+=v;
    __syncthreads();
  }
  if (t<Nn){ g_rowptr[t+1]=a[t]; g_cursor[t]=a[t]-g_cnt_raw[t]; }
  if (t==0) g_rowptr[0]=0;
}

__global__ void kfill(const int* __restrict__ eidx){
  int e = blockIdx.x*256+threadIdx.x;
  if (e<Ee){ int pos=atomicAdd(&g_cursor[eidx[Ee+e]],1); g_colidx[pos]=e; }
}

__global__ void kfix(const int* __restrict__ eidx){
  int t = blockIdx.x*256+threadIdx.x;
  if (t>=Nn) return;
  int rs=g_rowptr[t], re=g_rowptr[t+1];
  for (int i=rs+1;i<re;i++){
    int key=g_colidx[i]; int j=i-1;
    while(j>=rs && g_colidx[j]>key){ g_colidx[j+1]=g_colidx[j]; j--; }
    g_colidx[j+1]=key;
  }
  int w=rs;
  for (int i=rs;i<re;i++){
    int e=g_colidx[i]; int src=eidx[e];
    bool later=false;
    for (int j2=i+1;j2<re;j2++){ if (eidx[g_colidx[j2]]==src){later=true;break;} }
    if (!later) g_colidx[w++]=e;
  }
  g_cnt[t]=w-rs;
}

__global__ void khn(const float* __restrict__ pm25,
                    const float* __restrict__ Wn, const float* __restrict__ bn){
  __shared__ float red[256];
  int b=blockIdx.x, t=threadIdx.x;
  float w=Wn[0], bb=bn[0];
  float s=0.f;
  for (int n=t;n<Nn;n+=256){ float h=pm25[b*Nn+n]*w+bb; g_hn[b*Nn+n]=h; s+=h; }
  red[t]=s; __syncthreads();
  for(int off=128;off;off>>=1){ if(t<off) red[t]+=red[t+off]; __syncthreads(); }
  if(t==0) g_sumhn[b]=red[0];
}

// ---------------- main GRU+MLP: HMMA, h hi/lo reg-resident, W bf16 (2-pass) ----------------
__global__ void __launch_bounds__(256,1) kgru(
    const float* __restrict__ feature, const int* __restrict__ eidx,
    const float* __restrict__ eattr,   const float* __restrict__ wmean,
    const float* __restrict__ wstd,    const float* __restrict__ W_ih,
    const float* __restrict__ W_hh,    const float* __restrict__ b_ih,
    const float* __restrict__ b_hh,    const float* __restrict__ W1,
    const float* __restrict__ b1,      const float* __restrict__ W2,
    const float* __restrict__ b2)
{
  extern __shared__ uint32_t su[];
  float* sf = (float*)su;

  const int tid=threadIdx.x, wid=tid>>5, lane=tid&31;
  const int gq=lane>>2, tig=lane&3;
  const int base=blockIdx.x*256, bIdx=base/Ee, e0=base%Ee;

  // ---- build B-fragment images (bf16 hi only), exact mma register layout ----
  for (int idx=tid; idx<8192; idx+=256){
    int f=idx>>6, r6=idx&63, ln=r6>>1, reg=r6&1;
    int g2=ln>>2, t2=ln&3;
    float w0,w1;
    if (f<96){
      int kt=f&3, nt=(f>>2)&7, g=f>>5;
      int n = g*64 + nt*8 + g2;
      int k0 = kt*16 + t2*2 + reg*8;
      w0 = W_hh[k0*192+n]; w1 = W_hh[(k0+1)*192+n];
    } else {
      int f2=f-96, kt=f2&3, nt=(f2>>2)&7;
      int n = nt*8+g2;
      int k0 = kt*16 + t2*2 + reg*8;
      w0 = W1[k0*64+n]; w1 = W1[(k0+1)*64+n];
    }
    su[idx] = pk_bf2(w0,w1);
  }
  // ---- gi coefficient tables ----
  if (tid<192){
    int g=tid>>6, j=tid&63;
    float bias = b_ih[g*64+j] + (g==2 ? 0.f : b_hh[g*64+j]);
    float4 cf = make_float4(W_ih[g*64+j], W_ih[192+g*64+j], W_ih[384+g*64+j], bias);
    *(float4*)&sf[GI4_O + (g*64+j)*4] = cf;
  }
  if (tid<64){
    sf[BHN_O+tid] = b_hh[128+tid];
    sf[MB2_O+tid*2]   = b1[tid];
    sf[MB2_O+tid*2+1] = W2[tid];
  }
  {
    int e=e0+tid;
    ((int*)su)[SRC_O+tid]=eidx[e];
    float dd=eattr[2*e], dr=eattr[2*e+1];
    sf[DIR_O+tid]=dr;
    sf[C3D_O+tid]=3.f/dd;
    sf[EA0_O+tid]=(dd-g_stat[0])*g_stat[2];
    sf[EA1_O+tid]=(dr-g_stat[1])*g_stat[3];
  }
  const float wm0=wmean[0], wm1=wmean[1], ws0=wstd[0], ws1=wstd[1];
  const float b2v=b2[0];
  __syncthreads();

  float ea0v[4], ea1v[4];
  #pragma unroll
  for (int ri=0;ri<4;ri++){
    int row = wid*32 + (ri>>1)*16 + (ri&1)*8 + gq;
    ea0v[ri]=sf[EA0_O+row]; ea1v[ri]=sf[EA1_O+row];
  }

  uint32_t Ah[2][4][4], Al[2][4][4];
  #pragma unroll
  for(int rb=0;rb<2;rb++)
    #pragma unroll
    for(int kt=0;kt<4;kt++)
      #pragma unroll
      for(int r=0;r<4;r++){ Ah[rb][kt][r]=0u; Al[rb][kt][r]=0u; }

  float accA[2][8][4], accB[2][8][4];

  // 2-pass sweep: (Ahi + Alo) @ Bhi   (B weights bf16-rounded)
#define SWEEP(ACC,F) do{ \
  _Pragma("unroll") \
  for(int kt=0;kt<4;kt++){ \
    _Pragma("unroll") \
    for(int nt=0;nt<8;nt++){ \
      uint2 bh = *(const uint2*)&su[(((F)+nt*4+kt)<<6) + (lane<<1)]; \
      MMA(ACC[0][nt], Ah[0][kt], bh.x, bh.y); \
      MMA(ACC[0][nt], Al[0][kt], bh.x, bh.y); \
      MMA(ACC[1][nt], Ah[1][kt], bh.x, bh.y); \
      MMA(ACC[1][nt], Al[1][kt], bh.x, bh.y); \
    } \
  } \
}while(0)

#define ZERO(ACC) do{ \
  _Pragma("unroll") for(int rb=0;rb<2;rb++) \
  _Pragma("unroll") for(int nt=0;nt<8;nt++) \
  _Pragma("unroll") for(int c=0;c<4;c++) (ACC)[rb][nt][c]=0.f; \
}while(0)

  for (int t=0;t<Tt;t++){
    __syncthreads();
    {
      int s = ((const int*)su)[SRC_O+tid];
      const float* fp = feature + ((size_t)(bIdx*25+1+t)*Nn + s)*4 + 2;
      float speed = fp[0]*ws0+wm0;
      float wdir  = fp[1]*ws1+wm1;
      sf[EW_O+tid] = fmaxf(sf[C3D_O+tid]*speed*cosf(sf[DIR_O+tid]-wdir),0.f);
    }
    __syncthreads();
    float ewv[4];
    #pragma unroll
    for (int ri=0;ri<4;ri++) ewv[ri]=sf[EW_O + wid*32 + (ri>>1)*16 + (ri&1)*8 + gq];

    // ---- gate R -> accA becomes r ----
    ZERO(accA);
    SWEEP(accA, 0);
    #pragma unroll
    for(int nt=0;nt<8;nt++)
      #pragma unroll
      for(int par=0;par<2;par++){
        int j = nt*8 + tig*2 + par;
        float4 cf = *(const float4*)&sf[GI4_O + j*4];
        #pragma unroll
        for(int ri=0;ri<4;ri++){
          int rb=ri>>1, c=(ri&1)*2+par;
          float gi = ea0v[ri]*cf.x + ea1v[ri]*cf.y + ewv[ri]*cf.z + cf.w;
          accA[rb][nt][c] = sigfast(gi+accA[rb][nt][c]);
        }
      }
    // ---- gate N -> accB becomes n ----
    ZERO(accB);
    SWEEP(accB, 64);
    #pragma unroll
    for(int nt=0;nt<8;nt++)
      #pragma unroll
      for(int par=0;par<2;par++){
        int j = nt*8 + tig*2 + par;
        float4 cf = *(const float4*)&sf[GI4_O + (128+j)*4];
        float bhn = sf[BHN_O+j];
        #pragma unroll
        for(int ri=0;ri<4;ri++){
          int rb=ri>>1, c=(ri&1)*2+par;
          float gi = ea0v[ri]*cf.x + ea1v[ri]*cf.y + ewv[ri]*cf.z + cf.w;
          float pre = gi + accA[rb][nt][c]*(accB[rb][nt][c]+bhn);
          accB[rb][nt][c] = tanhfast(pre);
        }
      }
    // ---- gate Z -> accA; h_new into accA ----
    ZERO(accA);
    SWEEP(accA, 32);
    #pragma unroll
    for(int nt=0;nt<8;nt++)
      #pragma unroll
      for(int par=0;par<2;par++){
        int j = nt*8 + tig*2 + par;
        float4 cf = *(const float4*)&sf[GI4_O + (64+j)*4];
        #pragma unroll
        for(int ri=0;ri<4;ri++){
          int rb=ri>>1, c=(ri&1)*2+par;
          float gi = ea0v[ri]*cf.x + ea1v[ri]*cf.y + ewv[ri]*cf.z + cf.w;
          float z = sigfast(gi+accA[rb][nt][c]);
          int ridx = (nt&1)*2 + (c>>1);
          float hold = ubfh(Ah[rb][nt>>1][ridx], c&1) + ubfh(Al[rb][nt>>1][ridx], c&1);
          float n = accB[rb][nt][c];
          accA[rb][nt][c] = n + z*(hold-n);
        }
      }
    // ---- pack h_new -> A fragments ----
    #pragma unroll
    for(int rb=0;rb<2;rb++)
      #pragma unroll
      for(int kt=0;kt<4;kt++){
        pksplit(accA[rb][2*kt][0],  accA[rb][2*kt][1],  Ah[rb][kt][0], Al[rb][kt][0]);
        pksplit(accA[rb][2*kt][2],  accA[rb][2*kt][3],  Ah[rb][kt][1], Al[rb][kt][1]);
        pksplit(accA[rb][2*kt+1][0],accA[rb][2*kt+1][1],Ah[rb][kt][2], Al[rb][kt][2]);
        pksplit(accA[rb][2*kt+1][2],accA[rb][2*kt+1][3],Ah[rb][kt][3], Al[rb][kt][3]);
      }
    // ---- MLP: accB = h_new @ W1 ----
    ZERO(accB);
    SWEEP(accB, 96);
    float p[4] = {0.f,0.f,0.f,0.f};
    #pragma unroll
    for(int nt=0;nt<8;nt++)
      #pragma unroll
      for(int par=0;par<2;par++){
        int j = nt*8 + tig*2 + par;
        float bb1 = sf[MB2_O+j*2], ww2 = sf[MB2_O+j*2+1];
        #pragma unroll
        for(int ri=0;ri<4;ri++){
          int rb=ri>>1, c=(ri&1)*2+par;
          p[ri] += fmaxf(accB[rb][nt][c]+bb1,0.f)*ww2;
        }
      }
    #pragma unroll
    for(int ri=0;ri<4;ri++){
      p[ri] += __shfl_xor_sync(0xffffffffu,p[ri],1);
      p[ri] += __shfl_xor_sync(0xffffffffu,p[ri],2);
    }
    if (tig==0){
      #pragma unroll
      for(int ri=0;ri<4;ri++){
        int row = wid*32 + (ri>>1)*16 + (ri&1)*8 + gq;
        g_erep[t*BE + base + row] = p[ri]+b2v;
      }
    }
  }
#undef SWEEP
#undef ZERO
}

// ---------------- softmax rows of R + c_pred (proven) ----------------
__global__ void krow(const int* __restrict__ eidx, float* __restrict__ out)
{
  __shared__ float srow[8][Nn];
  const int wid = threadIdx.x>>5, lane=threadIdx.x&31;
  const int gid = blockIdx.x*8 + wid;
  const int tgt = gid % Nn;
  const int bt  = gid / Nn;
  const int t   = bt % Tt;
  const int b   = bt / Tt;
  const int rs  = g_rowptr[tgt];
  const int cnt = g_cnt[tgt];
  const float* er  = g_erep + (size_t)t*BE + (size_t)b*Ee;
  const float* hnb = g_hn + b*Nn;

  float vmax=0.f;
  for (int i=lane;i<cnt;i+=32){ float v=er[g_colidx[rs+i]]; vmax=fmaxf(vmax,v); }
  #pragma unroll
  for(int off=16;off;off>>=1) vmax=fmaxf(vmax,__shfl_xor_sync(0xffffffffu,vmax,off));

  float se=0.f, shw=0.f, shf=0.f;
  for (int i=lane;i<cnt;i+=32){
    int e=g_colidx[rs+i];
    float v=er[e];
    float ex=__expf(v-vmax);
    float hv=hnb[eidx[e]];
    se+=ex; shw+=ex*hv; shf+=hv;
  }
  #pragma unroll
  for(int off=16;off;off>>=1){
    se +=__shfl_xor_sync(0xffffffffu,se ,off);
    shw+=__shfl_xor_sync(0xffffffffu,shw,off);
    shf+=__shfl_xor_sync(0xffffffffu,shf,off);
  }
  float ez  = __expf(-vmax);
  float inv = __fdividef(1.f, (float)(Nn-cnt)*ez + se);
  float defv= ez*inv;
  if (lane==0) out[gid] = (ez*(g_sumhn[b]-shf)+shw)*inv;

  float* row = srow[wid];
  for (int s=lane;s<Nn;s+=32) row[s]=defv;
  __syncwarp();
  for (int i=lane;i<cnt;i+=32){
    int e=g_colidx[rs+i];
    row[eidx[e]] = __expf(er[e]-vmax)*inv;
  }
  __syncwarp();
  float* dst = out + PRED_ELEMS + (size_t)gid*Nn;
  float4* d4=(float4*)dst; const float4* s4=(const float4*)row;
  for (int s=lane;s<Nn/4;s+=32) d4[s]=s4[s];
}

// ---------------- launch (kgru is 4th app launch; +2 harness launches => ncu slot 6) ----------------
extern "C" void kernel_launch(void* const* d_in, const int* in_sizes, int n_in,
                              void* d_out, int out_size){
  const float* pm25   =(const float*)d_in[0];
  const float* feature=(const float*)d_in[1];
  const int*   eidx   =(const int*)  d_in[2];
  const float* eattr  =(const float*)d_in[3];
  const float* wmean  =(const float*)d_in[4];
  const float* wstd   =(const float*)d_in[5];
  const float* W_ih   =(const float*)d_in[6];
  const float* W_hh   =(const float*)d_in[7];
  const float* b_ih   =(const float*)d_in[8];
  const float* b_hh   =(const float*)d_in[9];
  const float* W1     =(const float*)d_in[10];
  const float* b1     =(const float*)d_in[11];
  const float* W2     =(const float*)d_in[12];
  const float* b2     =(const float*)d_in[13];
  const float* W_node =(const float*)d_in[14];
  const float* b_node =(const float*)d_in[15];
  float* out=(float*)d_out;

  cudaFuncSetAttribute(kgru, cudaFuncAttributeMaxDynamicSharedMemorySize, SMEM_SZ);

  kstat <<<1,1024>>>(eattr);
  kcount<<<96,256>>>(eidx);
  kscan <<<1,1024>>>();
  kgru  <<<768,256,SMEM_SZ>>>(feature,eidx,eattr,wmean,wstd,
                              W_ih,W_hh,b_ih,b_hh,W1,b1,W2,b2);
  kfill <<<96,256>>>(eidx);
  kfix  <<<3,256>>>(eidx);
  khn   <<<8,256>>>(pm25,W_node,b_node);
  krow  <<<18432,256>>>(eidx,out);
}

// round 15
// speedup vs baseline: 9.3756x; 1.4042x over previous
#include <cuda_runtime.h>
#include <cuda_bf16.h>
#include <math.h>
#include <stdint.h>

#define Bb 8
#define Tt 24
#define Nn 768
#define Ee 24576
#define Hh 64
#define BE 196608              // B*E
#define PRED_ELEMS (Bb*Tt*Nn)  // 147456

// ---------------- device scratch (static, no allocs) ----------------
__device__ float g_stat[4];
__device__ float g_hn[Bb*Nn];
__device__ float g_sumhn[Bb];
__device__ int   g_cnt_raw[Nn];
__device__ int   g_rowptr[Nn+1];
__device__ int   g_cursor[Nn];
__device__ int   g_colidx[Ee];
__device__ int   g_cnt[Nn];
__device__ float g_erep[Tt*BE];      // 18.9 MB

// ---------------- SMEM map (f32/u32 units) ----------------
// 0..9215 : B-fragment images (u32), 144 frags x 64 u32 (bf16)
//   Whh (g,nt,kt) = g*32+nt*4+kt  (g=0r,1z,2n) ; W1 = 96+nt*4+kt
//   x-frag R = 128+nt ; x-frag Z = 136+nt  (k0..6: Wih rows + bias hi/lo)
#define GI4_O  9216    // float4 per (g*64+j): {wih_f0, wih_f1, wih_f2, bias}
#define BHN_O  9984    // bhh n-part per j (64)
#define MB2_O  10048   // float2 per j: {b1, W2}
#define EA0_O  10176
#define EA1_O  10432
#define SMEM_F32 10688
#define SMEM_SZ  (SMEM_F32*4)   // 42752 B

// m16n8k16 bf16 mma (sm_80+ baseline)
#define MMA(D,A,b0,b1) \
  asm("mma.sync.aligned.m16n8k16.row.col.f32.bf16.bf16.f32 " \
      "{%0,%1,%2,%3}, {%4,%5,%6,%7}, {%8,%9}, {%0,%1,%2,%3};" \
      : "+f"((D)[0]),"+f"((D)[1]),"+f"((D)[2]),"+f"((D)[3]) \
      : "r"((A)[0]),"r"((A)[1]),"r"((A)[2]),"r"((A)[3]), "r"(b0),"r"(b1))

// x-kt mma: A regs 2,3 (k 8..15) are zero
#define MMAX(D,a0,a1,b0,b1) \
  asm("mma.sync.aligned.m16n8k16.row.col.f32.bf16.bf16.f32 " \
      "{%0,%1,%2,%3}, {%4,%5,%6,%7}, {%8,%9}, {%0,%1,%2,%3};" \
      : "+f"((D)[0]),"+f"((D)[1]),"+f"((D)[2]),"+f"((D)[3]) \
      : "r"(a0),"r"(a1),"r"(0u),"r"(0u), "r"(b0),"r"(b1))

__device__ __forceinline__ float tanhfast(float x){
  float y; asm("tanh.approx.f32 %0,%1;":"=f"(y):"f"(x)); return y;
}
__device__ __forceinline__ float sigfast(float x){
  return 0.5f*tanhfast(0.5f*x)+0.5f;
}
__device__ __forceinline__ float ubfh(uint32_t v, int hf){
  return __bfloat162float(__ushort_as_bfloat16((unsigned short)(hf?(v>>16):(v&0xffff))));
}
__device__ __forceinline__ uint32_t pk_bf2(float x, float y){  // {lo16=x, hi16=y}
  uint32_t r; asm("cvt.rn.bf16x2.f32 %0, %1, %2;":"=r"(r):"f"(y),"f"(x)); return r;
}
// {lo16=bf16(v), hi16=bf16(v-bf16(v))} : exact hi/lo pair of one scalar
__device__ __forceinline__ uint32_t split2(float v){
  float vh = __bfloat162float(__float2bfloat16(v));
  return pk_bf2(vh, v - vh);
}

// ---------------- prep kernels (proven) ----------------
__global__ void kstat(const float* __restrict__ eattr){
  __shared__ double red[1024];
  int tid = threadIdx.x;
  double s0=0,s1=0,q0=0,q1=0;
  for (int e=tid; e<Ee; e+=1024){
    double a=eattr[2*e], b=eattr[2*e+1];
    s0+=a; s1+=b; q0+=a*a; q1+=b*b;
  }
  double vals[4]={s0,s1,q0,q1};
  double out[4];
  for (int v=0; v<4; ++v){
    red[tid]=vals[v]; __syncthreads();
    for (int off=512; off; off>>=1){ if (tid<off) red[tid]+=red[tid+off]; __syncthreads(); }
    out[v]=red[0]; __syncthreads();
  }
  if (tid==0){
    double m0=out[0]/Ee, m1=out[1]/Ee;
    double v0=(out[2]-out[0]*out[0]/Ee)/(double)(Ee-1);
    double v1=(out[3]-out[1]*out[1]/Ee)/(double)(Ee-1);
    g_stat[0]=(float)m0; g_stat[1]=(float)m1;
    g_stat[2]=(float)(1.0/sqrt(v0)); g_stat[3]=(float)(1.0/sqrt(v1));
  }
  if (tid<Nn) g_cnt_raw[tid]=0;
}

__global__ void kcount(const int* __restrict__ eidx){
  int e = blockIdx.x*256+threadIdx.x;
  if (e<Ee) atomicAdd(&g_cnt_raw[eidx[Ee+e]],1);
}

__global__ void kscan(){
  __shared__ int a[Nn];
  int t=threadIdx.x;
  if (t<Nn) a[t]=g_cnt_raw[t];
  __syncthreads();
  for (int d=1; d<Nn; d<<=1){
    int v=0;
    if (t<Nn && t>=d) v=a[t-d];
    __syncthreads();
    if (t<Nn) a[t]+=v;
    __syncthreads();
  }
  if (t<Nn){ g_rowptr[t+1]=a[t]; g_cursor[t]=a[t]-g_cnt_raw[t]; }
  if (t==0) g_rowptr[0]=0;
}

__global__ void kfill(const int* __restrict__ eidx){
  int e = blockIdx.x*256+threadIdx.x;
  if (e<Ee){ int pos=atomicAdd(&g_cursor[eidx[Ee+e]],1); g_colidx[pos]=e; }
}

__global__ void kfix(const int* __restrict__ eidx){
  int t = blockIdx.x*256+threadIdx.x;
  if (t>=Nn) return;
  int rs=g_rowptr[t], re=g_rowptr[t+1];
  for (int i=rs+1;i<re;i++){
    int key=g_colidx[i]; int j=i-1;
    while(j>=rs && g_colidx[j]>key){ g_colidx[j+1]=g_colidx[j]; j--; }
    g_colidx[j+1]=key;
  }
  int w=rs;
  for (int i=rs;i<re;i++){
    int e=g_colidx[i]; int src=eidx[e];
    bool later=false;
    for (int j2=i+1;j2<re;j2++){ if (eidx[g_colidx[j2]]==src){later=true;break;} }
    if (!later) g_colidx[w++]=e;
  }
  g_cnt[t]=w-rs;
}

__global__ void khn(const float* __restrict__ pm25,
                    const float* __restrict__ Wn, const float* __restrict__ bn){
  __shared__ float red[256];
  int b=blockIdx.x, t=threadIdx.x;
  float w=Wn[0], bb=bn[0];
  float s=0.f;
  for (int n=t;n<Nn;n+=256){ float h=pm25[b*Nn+n]*w+bb; g_hn[b*Nn+n]=h; s+=h; }
  red[t]=s; __syncthreads();
  for(int off=128;off;off>>=1){ if(t<off) red[t]+=red[t+off]; __syncthreads(); }
  if(t==0) g_sumhn[b]=red[0];
}

// ---------------- main GRU+MLP: HMMA bf16, free-running warps, gi folded into MMA ----------------
__global__ void __launch_bounds__(256,1) kgru(
    const float* __restrict__ feature, const int* __restrict__ eidx,
    const float* __restrict__ eattr,   const float* __restrict__ wmean,
    const float* __restrict__ wstd,    const float* __restrict__ W_ih,
    const float* __restrict__ W_hh,    const float* __restrict__ b_ih,
    const float* __restrict__ b_hh,    const float* __restrict__ W1,
    const float* __restrict__ b1,      const float* __restrict__ W2,
    const float* __restrict__ b2)
{
  extern __shared__ uint32_t su[];
  float* sf = (float*)su;

  const int tid=threadIdx.x, wid=tid>>5, lane=tid&31;
  const int gq=lane>>2, tig=lane&3;
  const int base=blockIdx.x*256, bIdx=base/Ee, e0=base%Ee;

  // ---- build B-fragment images (bf16), exact mma register layout ----
  for (int idx=tid; idx<9216; idx+=256){
    int f=idx>>6, r6=idx&63, ln=r6>>1, reg=r6&1;
    int g2=ln>>2, t2=ln&3;
    uint32_t val;
    if (f<96){
      int kt=f&3, nt=(f>>2)&7, g=f>>5;
      int n = g*64 + nt*8 + g2;
      int k0 = kt*16 + t2*2 + reg*8;
      val = pk_bf2(W_hh[k0*192+n], W_hh[(k0+1)*192+n]);
    } else if (f<128){
      int f2=f-96, kt=f2&3, nt=(f2>>2)&7;
      int n = nt*8+g2;
      int k0 = kt*16 + t2*2 + reg*8;
      val = pk_bf2(W1[k0*64+n], W1[(k0+1)*64+n]);
    } else {
      // x-frags: k slots 0..5 = Wih rows (dup pairs), 6..7 = bias hi/lo, 8..15 = 0
      if (reg==1) val = 0u;
      else {
        int g = (f<136)?0:1;          // R or Z
        int j = (f&7)*8 + g2;
        if (t2<3){ float w = W_ih[t2*192 + g*64 + j]; val = pk_bf2(w,w); }
        else {
          float bs = b_ih[g*64+j] + b_hh[g*64+j];
          float bh_ = __bfloat162float(__float2bfloat16(bs));
          val = pk_bf2(bh_, bs-bh_);
        }
      }
    }
    su[idx]=val;
  }
  // ---- gi coefficient table (used only for gate N) + small tables ----
  if (tid<192){
    int g=tid>>6, j=tid&63;
    float bias = b_ih[g*64+j] + (g==2 ? 0.f : b_hh[g*64+j]);
    float4 cf = make_float4(W_ih[g*64+j], W_ih[192+g*64+j], W_ih[384+g*64+j], bias);
    *(float4*)&sf[GI4_O + (g*64+j)*4] = cf;
  }
  if (tid<64){
    sf[BHN_O+tid] = b_hh[128+tid];
    sf[MB2_O+tid*2]   = b1[tid];
    sf[MB2_O+tid*2+1] = W2[tid];
  }
  // per-edge constants (own row = base+tid)
  const int   s_reg = eidx[e0+tid];
  const float dd = eattr[2*(e0+tid)], dr = eattr[2*(e0+tid)+1];
  const float dir_reg = dr, c3d_reg = 3.f/dd;
  sf[EA0_O+tid]=(dd-g_stat[0])*g_stat[2];
  sf[EA1_O+tid]=(dr-g_stat[1])*g_stat[3];
  const float wm0=wmean[0], wm1=wmean[1], ws0=wstd[0], ws1=wstd[1];
  const float b2v=b2[0];
  __syncthreads();

  float ea0v[4], ea1v[4];
  #pragma unroll
  for (int ri=0;ri<4;ri++){
    int row = wid*32 + (ri>>1)*16 + (ri&1)*8 + gq;
    ea0v[ri]=sf[EA0_O+row]; ea1v[ri]=sf[EA1_O+row];
  }

  // constant part of the x A-fragment (tig 0:ea0, 1:ea1, 3:(1,1); tig 2 per-step)
  uint32_t xc[2][2];
  #pragma unroll
  for (int rb=0;rb<2;rb++)
    #pragma unroll
    for (int ch=0;ch<2;ch++){
      int ri=rb*2+ch;
      xc[rb][ch] = (tig==0)? split2(ea0v[ri])
                 : (tig==1)? split2(ea1v[ri])
                 : (tig==3)? 0x3F803F80u : 0u;
    }

  uint32_t Ah[2][4][4];
  #pragma unroll
  for(int rb=0;rb<2;rb++)
    #pragma unroll
    for(int kt=0;kt<4;kt++)
      #pragma unroll
      for(int r=0;r<4;r++) Ah[rb][kt][r]=0u;

  float accA[2][8][4], accB[2][8][4];

#define SWEEP(ACC,F) do{ \
  _Pragma("unroll") \
  for(int kt=0;kt<4;kt++){ \
    _Pragma("unroll") \
    for(int nt=0;nt<8;nt++){ \
      uint2 bh = *(const uint2*)&su[(((F)+nt*4+kt)<<6) + (lane<<1)]; \
      MMA(ACC[0][nt], Ah[0][kt], bh.x, bh.y); \
      MMA(ACC[1][nt], Ah[1][kt], bh.x, bh.y); \
    } \
  } \
}while(0)

#define XSWEEP(ACC,XF) do{ \
  _Pragma("unroll") \
  for(int nt=0;nt<8;nt++){ \
    uint2 bx = *(const uint2*)&su[(((XF)+nt)<<6) + (lane<<1)]; \
    MMAX(ACC[0][nt], xa[0][0], xa[0][1], bx.x, bx.y); \
    MMAX(ACC[1][nt], xa[1][0], xa[1][1], bx.x, bx.y); \
  } \
}while(0)

#define ZERO(ACC) do{ \
  _Pragma("unroll") for(int rb=0;rb<2;rb++) \
  _Pragma("unroll") for(int nt=0;nt<8;nt++) \
  _Pragma("unroll") for(int c=0;c<4;c++) (ACC)[rb][nt][c]=0.f; \
}while(0)

  const float* fp = feature + ((size_t)(bIdx*25+1)*Nn + s_reg)*4 + 2;

  for (int t=0;t<Tt;t++){
    // edge weight for own row, broadcast within warp (no block sync!)
    float2 wv = *(const float2*)fp; fp += Nn*4;
    float speed = wv.x*ws0+wm0;
    float wdir  = wv.y*ws1+wm1;
    float myew = fmaxf(c3d_reg*speed*cosf(dir_reg-wdir), 0.f);
    float ewv[4];
    #pragma unroll
    for (int ri=0;ri<4;ri++)
      ewv[ri] = __shfl_sync(0xffffffffu, myew, (ri>>1)*16 + (ri&1)*8 + gq);
    uint32_t xa[2][2];
    #pragma unroll
    for (int rb=0;rb<2;rb++)
      #pragma unroll
      for (int ch=0;ch<2;ch++)
        xa[rb][ch] = (tig==2)? split2(ewv[rb*2+ch]) : xc[rb][ch];

    // ---- gate R (gi folded) -> accA becomes r ----
    ZERO(accA);
    SWEEP(accA, 0);
    XSWEEP(accA, 128);
    #pragma unroll
    for(int rb=0;rb<2;rb++)
      #pragma unroll
      for(int nt=0;nt<8;nt++)
        #pragma unroll
        for(int c=0;c<4;c++)
          accA[rb][nt][c] = sigfast(accA[rb][nt][c]);

    // ---- gate N (scalar gi) -> accB becomes n ----
    ZERO(accB);
    SWEEP(accB, 64);
    #pragma unroll
    for(int nt=0;nt<8;nt++)
      #pragma unroll
      for(int par=0;par<2;par++){
        int j = nt*8 + tig*2 + par;
        float4 cf = *(const float4*)&sf[GI4_O + (128+j)*4];
        float bhn = sf[BHN_O+j];
        #pragma unroll
        for(int ri=0;ri<4;ri++){
          int rb=ri>>1, c=(ri&1)*2+par;
          float gi = ea0v[ri]*cf.x + ea1v[ri]*cf.y + ewv[ri]*cf.z + cf.w;
          float pre = gi + accA[rb][nt][c]*(accB[rb][nt][c]+bhn);
          accB[rb][nt][c] = tanhfast(pre);
        }
      }

    // ---- gate Z (gi folded) -> accA; h_new into accA ----
    ZERO(accA);
    SWEEP(accA, 32);
    XSWEEP(accA, 136);
    #pragma unroll
    for(int nt=0;nt<8;nt++)
      #pragma unroll
      for(int par=0;par<2;par++){
        #pragma unroll
        for(int ri=0;ri<4;ri++){
          int rb=ri>>1, c=(ri&1)*2+par;
          float z = sigfast(accA[rb][nt][c]);
          int ridx = (nt&1)*2 + (c>>1);
          float hold = ubfh(Ah[rb][nt>>1][ridx], c&1);
          float n = accB[rb][nt][c];
          accA[rb][nt][c] = n + z*(hold-n);
        }
      }

    // ---- pack h_new -> A fragments (plain bf16) ----
    #pragma unroll
    for(int rb=0;rb<2;rb++)
      #pragma unroll
      for(int kt=0;kt<4;kt++){
        Ah[rb][kt][0] = pk_bf2(accA[rb][2*kt][0],  accA[rb][2*kt][1]);
        Ah[rb][kt][1] = pk_bf2(accA[rb][2*kt][2],  accA[rb][2*kt][3]);
        Ah[rb][kt][2] = pk_bf2(accA[rb][2*kt+1][0],accA[rb][2*kt+1][1]);
        Ah[rb][kt][3] = pk_bf2(accA[rb][2*kt+1][2],accA[rb][2*kt+1][3]);
      }

    // ---- MLP: accB = h_new @ W1 ----
    ZERO(accB);
    SWEEP(accB, 96);
    float p[4] = {0.f,0.f,0.f,0.f};
    #pragma unroll
    for(int nt=0;nt<8;nt++)
      #pragma unroll
      for(int par=0;par<2;par++){
        int j = nt*8 + tig*2 + par;
        float bb1 = sf[MB2_O+j*2], ww2 = sf[MB2_O+j*2+1];
        #pragma unroll
        for(int ri=0;ri<4;ri++){
          int rb=ri>>1, c=(ri&1)*2+par;
          p[ri] += fmaxf(accB[rb][nt][c]+bb1,0.f)*ww2;
        }
      }
    #pragma unroll
    for(int ri=0;ri<4;ri++){
      p[ri] += __shfl_xor_sync(0xffffffffu,p[ri],1);
      p[ri] += __shfl_xor_sync(0xffffffffu,p[ri],2);
    }
    if (tig==0){
      #pragma unroll
      for(int ri=0;ri<4;ri++){
        int row = wid*32 + (ri>>1)*16 + (ri&1)*8 + gq;
        g_erep[t*BE + base + row] = p[ri]+b2v;
      }
    }
  }
#undef SWEEP
#undef XSWEEP
#undef ZERO
}

// ---------------- softmax rows of R + c_pred (proven) ----------------
__global__ void krow(const int* __restrict__ eidx, float* __restrict__ out)
{
  __shared__ float srow[8][Nn];
  const int wid = threadIdx.x>>5, lane=threadIdx.x&31;
  const int gid = blockIdx.x*8 + wid;
  const int tgt = gid % Nn;
  const int bt  = gid / Nn;
  const int t   = bt % Tt;
  const int b   = bt / Tt;
  const int rs  = g_rowptr[tgt];
  const int cnt = g_cnt[tgt];
  const float* er  = g_erep + (size_t)t*BE + (size_t)b*Ee;
  const float* hnb = g_hn + b*Nn;

  float vmax=0.f;
  for (int i=lane;i<cnt;i+=32){ float v=er[g_colidx[rs+i]]; vmax=fmaxf(vmax,v); }
  #pragma unroll
  for(int off=16;off;off>>=1) vmax=fmaxf(vmax,__shfl_xor_sync(0xffffffffu,vmax,off));

  float se=0.f, shw=0.f, shf=0.f;
  for (int i=lane;i<cnt;i+=32){
    int e=g_colidx[rs+i];
    float v=er[e];
    float ex=__expf(v-vmax);
    float hv=hnb[eidx[e]];
    se+=ex; shw+=ex*hv; shf+=hv;
  }
  #pragma unroll
  for(int off=16;off;off>>=1){
    se +=__shfl_xor_sync(0xffffffffu,se ,off);
    shw+=__shfl_xor_sync(0xffffffffu,shw,off);
    shf+=__shfl_xor_sync(0xffffffffu,shf,off);
  }
  float ez  = __expf(-vmax);
  float inv = __fdividef(1.f, (float)(Nn-cnt)*ez + se);
  float defv= ez*inv;
  if (lane==0) out[gid] = (ez*(g_sumhn[b]-shf)+shw)*inv;

  float* row = srow[wid];
  for (int s=lane;s<Nn;s+=32) row[s]=defv;
  __syncwarp();
  for (int i=lane;i<cnt;i+=32){
    int e=g_colidx[rs+i];
    row[eidx[e]] = __expf(er[e]-vmax)*inv;
  }
  __syncwarp();
  float* dst = out + PRED_ELEMS + (size_t)gid*Nn;
  float4* d4=(float4*)dst; const float4* s4=(const float4*)row;
  for (int s=lane;s<Nn/4;s+=32) d4[s]=s4[s];
}

// ---------------- launch (kgru 4th app launch => ncu slot 6) ----------------
extern "C" void kernel_launch(void* const* d_in, const int* in_sizes, int n_in,
                              void* d_out, int out_size){
  const float* pm25   =(const float*)d_in[0];
  const float* feature=(const float*)d_in[1];
  const int*   eidx   =(const int*)  d_in[2];
  const float* eattr  =(const float*)d_in[3];
  const float* wmean  =(const float*)d_in[4];
  const float* wstd   =(const float*)d_in[5];
  const float* W_ih   =(const float*)d_in[6];
  const float* W_hh   =(const float*)d_in[7];
  const float* b_ih   =(const float*)d_in[8];
  const float* b_hh   =(const float*)d_in[9];
  const float* W1     =(const float*)d_in[10];
  const float* b1     =(const float*)d_in[11];
  const float* W2     =(const float*)d_in[12];
  const float* b2     =(const float*)d_in[13];
  const float* W_node =(const float*)d_in[14];
  const float* b_node =(const float*)d_in[15];
  float* out=(float*)d_out;

  cudaFuncSetAttribute(kgru, cudaFuncAttributeMaxDynamicSharedMemorySize, SMEM_SZ);

  kstat <<<1,1024>>>(eattr);
  kcount<<<96,256>>>(eidx);
  kscan <<<1,1024>>>();
  kgru  <<<768,256,SMEM_SZ>>>(feature,eidx,eattr,wmean,wstd,
                              W_ih,W_hh,b_ih,b_hh,W1,b1,W2,b2);
  kfill <<<96,256>>>(eidx);
  kfix  <<<3,256>>>(eidx);
  khn   <<<8,256>>>(pm25,W_node,b_node);
  krow  <<<18432,256>>>(eidx,out);
}